// round 4
// baseline (speedup 1.0000x reference)
#include <cuda_runtime.h>
#include <math.h>

// ---------------- scratch (static device globals; no allocations) ----------
__device__ float g_x   [4096*512];
__device__ float g_x2  [4096*512];
__device__ float g_ln  [4096*512];
__device__ float g_qkv [4096*1536];
__device__ float g_mlp [4096*2048];
__device__ float g_q   [64*1024*32];
__device__ float g_k   [64*1024*32];
__device__ float g_v   [64*1024*32];
__device__ float g_s   [64UL*1024*1024];   // 268 MB scores
__device__ float g_o   [4096*512];
__device__ float g_fin [4096*1024];
__device__ float g_img [4*64*128*128];
__device__ float g_c1  [4*16*128*128];

// ---------------- pos-embed add -------------------------------------------
__global__ void add_pe_kernel(const float* __restrict__ x, float* __restrict__ out) {
    int idx = blockIdx.x * blockDim.x + threadIdx.x;
    if (idx >= 4 * 1024 * 512) return;
    int c = idx & 511;
    int p = (idx >> 9) & 1023;
    int i = p >> 5, j = p & 31;
    int pos = (c < 256) ? j : i;   // first 256 ch use w-coord (grid[0]), last 256 use h
    int cc = c & 255;
    int m = cc & 127;
    double om = pow(10000.0, -(double)m / 128.0);
    double a = (double)pos * om;
    float pe = (cc < 128) ? (float)sin(a) : (float)cos(a);
    out[idx] = x[idx] + pe;
}

// ---------------- layernorm over rows of 512 ------------------------------
__global__ void ln_kernel(const float* __restrict__ in, const float* __restrict__ g,
                          const float* __restrict__ b, float* __restrict__ out,
                          float eps) {
    int row = blockIdx.x;
    const float* x = in + (size_t)row * 512;
    int t = threadIdx.x;                       // 128 threads
    float v[4];
    float s = 0.f;
#pragma unroll
    for (int i = 0; i < 4; i++) { v[i] = x[t + i * 128]; s += v[i]; }
    __shared__ float red[128];
    red[t] = s; __syncthreads();
    for (int o = 64; o > 0; o >>= 1) { if (t < o) red[t] += red[t + o]; __syncthreads(); }
    float mu = red[0] * (1.f / 512.f);
    __syncthreads();
    float sq = 0.f;
#pragma unroll
    for (int i = 0; i < 4; i++) { float d = v[i] - mu; sq += d * d; }
    red[t] = sq; __syncthreads();
    for (int o = 64; o > 0; o >>= 1) { if (t < o) red[t] += red[t + o]; __syncthreads(); }
    float rstd = rsqrtf(red[0] * (1.f / 512.f) + eps);
#pragma unroll
    for (int i = 0; i < 4; i++) {
        int c = t + i * 128;
        float y = (v[i] - mu) * rstd;
        if (g) y = y * g[c] + b[c];
        out[(size_t)row * 512 + c] = y;
    }
}

// ---------------- generic SGEMM, C = A(MxK) * B(KxN) + bias [+res|gelu] ---
// mode: 0 = bias, 1 = bias+residual, 2 = bias+GELU(exact)
__global__ void sgemm_kernel(const float* __restrict__ A, const float* __restrict__ B,
                             const float* __restrict__ bias, const float* __restrict__ res,
                             float* __restrict__ C, int M, int N, int K, int mode) {
    __shared__ float As[16][65];
    __shared__ float Bs[16][64];
    int tid = threadIdx.x;                 // 256 threads
    int tx = tid & 15, ty = tid >> 4;
    int bm = blockIdx.y * 64, bn = blockIdx.x * 64;
    const float* Ab = A + (size_t)bm * K;
    const float* Bb = B + bn;
    float acc[4][4] = {};
    for (int k0 = 0; k0 < K; k0 += 16) {
#pragma unroll
        for (int i = 0; i < 4; i++) {
            int idx = tid + i * 256;
            int r = idx >> 4, c = idx & 15;
            As[c][r] = Ab[(size_t)r * K + k0 + c];
            int rb = idx >> 6, cb = idx & 63;
            Bs[rb][cb] = Bb[(size_t)(k0 + rb) * N + cb];
        }
        __syncthreads();
#pragma unroll
        for (int kk = 0; kk < 16; kk++) {
            float ra[4], rb[4];
#pragma unroll
            for (int i = 0; i < 4; i++) ra[i] = As[kk][ty * 4 + i];
#pragma unroll
            for (int j = 0; j < 4; j++) rb[j] = Bs[kk][tx * 4 + j];
#pragma unroll
            for (int i = 0; i < 4; i++)
#pragma unroll
                for (int j = 0; j < 4; j++) acc[i][j] += ra[i] * rb[j];
        }
        __syncthreads();
    }
#pragma unroll
    for (int i = 0; i < 4; i++) {
        int row = bm + ty * 4 + i;
#pragma unroll
        for (int j = 0; j < 4; j++) {
            int col = bn + tx * 4 + j;
            float v = acc[i][j] + bias[col];
            if (mode == 1) v += res[(size_t)row * N + col];
            else if (mode == 2) v = 0.5f * v * (1.f + erff(v * 0.70710678118654752f));
            C[(size_t)row * N + col] = v;
        }
    }
}

// ---------------- qkv split to heads + q/k head-layernorm (HEAD_D = 32) ---
__global__ void qkv_split_kernel(const float* __restrict__ qkv,
                                 const float* __restrict__ nqg, const float* __restrict__ nqb,
                                 const float* __restrict__ nkg, const float* __restrict__ nkb,
                                 float* __restrict__ q, float* __restrict__ k,
                                 float* __restrict__ v) {
    int warp = (blockIdx.x * blockDim.x + threadIdx.x) >> 5;
    int lane = threadIdx.x & 31;
    if (warp >= 4096 * 16) return;
    int t = warp >> 4;          // token 0..4095
    int h = warp & 15;
    int b = t >> 10, n = t & 1023;
    const float* base = qkv + (size_t)t * 1536 + h * 32;
    float qv = base[lane];
    float kv = base[512 + lane];
    float vv = base[1024 + lane];

    float sq = qv, sk = kv;
#pragma unroll
    for (int o = 16; o > 0; o >>= 1) {
        sq += __shfl_xor_sync(0xffffffffu, sq, o);
        sk += __shfl_xor_sync(0xffffffffu, sk, o);
    }
    float mq = sq * (1.f / 32.f), mk = sk * (1.f / 32.f);
    float dq = qv - mq, dk = kv - mk;
    float vq = dq * dq, vk = dk * dk;
#pragma unroll
    for (int o = 16; o > 0; o >>= 1) {
        vq += __shfl_xor_sync(0xffffffffu, vq, o);
        vk += __shfl_xor_sync(0xffffffffu, vk, o);
    }
    float rq = rsqrtf(vq * (1.f / 32.f) + 1e-5f);
    float rk = rsqrtf(vk * (1.f / 32.f) + 1e-5f);
    size_t ob = ((size_t)(b * 16 + h) * 1024 + n) * 32;
    q[ob + lane] = dq * rq * nqg[lane] + nqb[lane];
    k[ob + lane] = dk * rk * nkg[lane] + nkb[lane];
    v[ob + lane] = vv;
}

// ---------------- scores: S = Q K^T / sqrt(32)  (batched over 64 bh) ------
__global__ void scores_kernel(const float* __restrict__ q, const float* __restrict__ k,
                              float* __restrict__ s) {
    int bh = blockIdx.z;
    int bm = blockIdx.y * 64, bn = blockIdx.x * 64;
    __shared__ float Qs[64][33];
    __shared__ float Ks[64][33];
    int tid = threadIdx.x;                 // 256
    const float* qb = q + ((size_t)bh * 1024 + bm) * 32;
    const float* kb = k + ((size_t)bh * 1024 + bn) * 32;
#pragma unroll
    for (int i = 0; i < 8; i++) {
        int idx = tid + i * 256;
        int r = idx >> 5, c = idx & 31;
        Qs[r][c] = qb[r * 32 + c];
        Ks[r][c] = kb[r * 32 + c];
    }
    __syncthreads();
    int tx = tid & 15, ty = tid >> 4;
    float acc[4][4] = {};
#pragma unroll
    for (int d = 0; d < 32; d++) {
        float ra[4], rb[4];
#pragma unroll
        for (int i = 0; i < 4; i++) ra[i] = Qs[ty * 4 + i][d];
#pragma unroll
        for (int j = 0; j < 4; j++) rb[j] = Ks[tx * 4 + j][d];
#pragma unroll
        for (int i = 0; i < 4; i++)
#pragma unroll
            for (int j = 0; j < 4; j++) acc[i][j] += ra[i] * rb[j];
    }
    const float sc = 0.17677669529663689f;   // 1/sqrt(32)
#pragma unroll
    for (int i = 0; i < 4; i++)
#pragma unroll
        for (int j = 0; j < 4; j++)
            s[((size_t)bh * 1024 + bm + ty * 4 + i) * 1024 + bn + tx * 4 + j] =
                acc[i][j] * sc;
}

// ---------------- row softmax over 1024 -----------------------------------
__global__ void softmax_kernel(float* __restrict__ s) {
    size_t row = blockIdx.x;
    float* p = s + row * 1024;
    int t = threadIdx.x;                      // 256 threads
    float v[4];
    float mx = -1e30f;
#pragma unroll
    for (int i = 0; i < 4; i++) { v[i] = p[t + i * 256]; mx = fmaxf(mx, v[i]); }
    __shared__ float red[256];
    red[t] = mx; __syncthreads();
    for (int o = 128; o > 0; o >>= 1) { if (t < o) red[t] = fmaxf(red[t], red[t + o]); __syncthreads(); }
    mx = red[0];
    __syncthreads();
    float sum = 0.f;
#pragma unroll
    for (int i = 0; i < 4; i++) { v[i] = expf(v[i] - mx); sum += v[i]; }
    red[t] = sum; __syncthreads();
    for (int o = 128; o > 0; o >>= 1) { if (t < o) red[t] += red[t + o]; __syncthreads(); }
    float inv = 1.f / red[0];
#pragma unroll
    for (int i = 0; i < 4; i++) p[t + i * 256] = v[i] * inv;
}

// ---------------- O = attn @ V, written to merged-head layout (d=32) ------
__global__ void av_kernel(const float* __restrict__ s, const float* __restrict__ v,
                          float* __restrict__ o) {
    int bh = blockIdx.y;
    int bm = blockIdx.x * 64;
    int b = bh >> 4, h = bh & 15;
    __shared__ float As[64][65];
    __shared__ float Vs[64][33];
    int tid = threadIdx.x;                 // 256
    int tx = tid & 15, ty = tid >> 4;      // cols tx*2..+1, rows ty*4..+3
    float acc[4][2] = {};
    for (int k0 = 0; k0 < 1024; k0 += 64) {
#pragma unroll
        for (int i = 0; i < 16; i++) {
            int idx = tid + i * 256;
            int r = idx >> 6, c = idx & 63;
            As[r][c] = s[((size_t)bh * 1024 + bm + r) * 1024 + k0 + c];
        }
#pragma unroll
        for (int i = 0; i < 8; i++) {
            int idx = tid + i * 256;
            int r = idx >> 5, c = idx & 31;
            Vs[r][c] = v[((size_t)bh * 1024 + k0 + r) * 32 + c];
        }
        __syncthreads();
#pragma unroll 8
        for (int kk = 0; kk < 64; kk++) {
            float ra[4], rb[2];
#pragma unroll
            for (int i = 0; i < 4; i++) ra[i] = As[ty * 4 + i][kk];
#pragma unroll
            for (int j = 0; j < 2; j++) rb[j] = Vs[kk][tx * 2 + j];
#pragma unroll
            for (int i = 0; i < 4; i++)
#pragma unroll
                for (int j = 0; j < 2; j++) acc[i][j] += ra[i] * rb[j];
        }
        __syncthreads();
    }
#pragma unroll
    for (int i = 0; i < 4; i++) {
        int n = bm + ty * 4 + i;
#pragma unroll
        for (int j = 0; j < 2; j++)
            o[((size_t)(b * 1024 + n)) * 512 + h * 32 + tx * 2 + j] = acc[i][j];
    }
}

// ---------------- unpatchify ----------------------------------------------
__global__ void unpatch_kernel(const float* __restrict__ fin, float* __restrict__ img) {
    int idx = blockIdx.x * blockDim.x + threadIdx.x;   // 4*64*128*128
    if (idx >= 4 * 64 * 128 * 128) return;
    int W = idx & 127;
    int H = (idx >> 7) & 127;
    int c = (idx >> 14) & 63;
    int b = idx >> 20;
    int hh = H >> 2, p = H & 3, ww = W >> 2, qq = W & 3;
    img[idx] = fin[((size_t)(b * 1024 + hh * 32 + ww)) * 1024 + c * 16 + p * 4 + qq];
}

// ---------------- direct 3x3 convs ----------------------------------------
__global__ void conv1_kernel(const float* __restrict__ img, const float* __restrict__ w,
                             const float* __restrict__ bias, float* __restrict__ out) {
    int idx = blockIdx.x * blockDim.x + threadIdx.x;   // 4*16*128*128
    if (idx >= 4 * 16 * 128 * 128) return;
    int x = idx & 127, y = (idx >> 7) & 127, oc = (idx >> 14) & 15, b = idx >> 18;
    float acc = bias[oc];
    for (int ic = 0; ic < 64; ic++) {
        const float* ip = img + ((size_t)(b * 64 + ic)) * 16384;
        const float* wp = w + (size_t)(oc * 64 + ic) * 9;
#pragma unroll
        for (int ky = 0; ky < 3; ky++) {
            int yy = y + ky - 1;
            if (yy < 0 || yy > 127) continue;
#pragma unroll
            for (int kx = 0; kx < 3; kx++) {
                int xx = x + kx - 1;
                if (xx < 0 || xx > 127) continue;
                acc += ip[yy * 128 + xx] * wp[ky * 3 + kx];
            }
        }
    }
    out[idx] = fmaxf(acc, 0.f);
}

__global__ void conv2_kernel(const float* __restrict__ img, const float* __restrict__ w,
                             const float* __restrict__ bias, float* __restrict__ out) {
    int idx = blockIdx.x * blockDim.x + threadIdx.x;   // 4*3*128*128
    if (idx >= 4 * 3 * 128 * 128) return;
    int x = idx & 127, y = (idx >> 7) & 127;
    int oc = (idx >> 14) % 3, b = idx / (3 * 16384);
    float acc = bias[oc];
    for (int ic = 0; ic < 16; ic++) {
        const float* ip = img + ((size_t)(b * 16 + ic)) * 16384;
        const float* wp = w + (size_t)(oc * 16 + ic) * 9;
#pragma unroll
        for (int ky = 0; ky < 3; ky++) {
            int yy = y + ky - 1;
            if (yy < 0 || yy > 127) continue;
#pragma unroll
            for (int kx = 0; kx < 3; kx++) {
                int xx = x + kx - 1;
                if (xx < 0 || xx > 127) continue;
                acc += ip[yy * 128 + xx] * wp[ky * 3 + kx];
            }
        }
    }
    out[idx] = acc;
}

// ---------------- driver ---------------------------------------------------
extern "C" void kernel_launch(void* const* d_in, const int* in_sizes, int n_in,
                              void* d_out, int out_size) {
    const float* x_in  = (const float*)d_in[0];
    const float* qkv_w = (const float*)d_in[1];
    const float* qkv_b = (const float*)d_in[2];
    const float* proj_w= (const float*)d_in[3];
    const float* proj_b= (const float*)d_in[4];
    const float* nq_g  = (const float*)d_in[5];
    const float* nq_b  = (const float*)d_in[6];
    const float* nk_g  = (const float*)d_in[7];
    const float* nk_b  = (const float*)d_in[8];
    const float* n1_g  = (const float*)d_in[9];
    const float* n1_b  = (const float*)d_in[10];
    const float* n2_g  = (const float*)d_in[11];
    const float* n2_b  = (const float*)d_in[12];
    const float* fc1_w = (const float*)d_in[13];
    const float* fc1_b = (const float*)d_in[14];
    const float* fc2_w = (const float*)d_in[15];
    const float* fc2_b = (const float*)d_in[16];
    const float* fin_w = (const float*)d_in[17];
    const float* fin_b = (const float*)d_in[18];
    const float* c1_w  = (const float*)d_in[19];
    const float* c1_b  = (const float*)d_in[20];
    const float* c2_w  = (const float*)d_in[21];
    const float* c2_b  = (const float*)d_in[22];
    float* out = (float*)d_out;

    float *px, *px2, *pln, *pqkv, *pmlp, *pq, *pk, *pv, *ps, *po, *pfin, *pimg, *pc1;
    cudaGetSymbolAddress((void**)&px,   g_x);
    cudaGetSymbolAddress((void**)&px2,  g_x2);
    cudaGetSymbolAddress((void**)&pln,  g_ln);
    cudaGetSymbolAddress((void**)&pqkv, g_qkv);
    cudaGetSymbolAddress((void**)&pmlp, g_mlp);
    cudaGetSymbolAddress((void**)&pq,   g_q);
    cudaGetSymbolAddress((void**)&pk,   g_k);
    cudaGetSymbolAddress((void**)&pv,   g_v);
    cudaGetSymbolAddress((void**)&ps,   g_s);
    cudaGetSymbolAddress((void**)&po,   g_o);
    cudaGetSymbolAddress((void**)&pfin, g_fin);
    cudaGetSymbolAddress((void**)&pimg, g_img);
    cudaGetSymbolAddress((void**)&pc1,  g_c1);

    add_pe_kernel<<<(4 * 1024 * 512 + 255) / 256, 256>>>(x_in, px);

    for (int l = 0; l < 8; l++) {
        const float* qw = qkv_w + (size_t)l * 512 * 1536;
        const float* qb = qkv_b + (size_t)l * 1536;
        const float* pw = proj_w + (size_t)l * 512 * 512;
        const float* pb = proj_b + (size_t)l * 512;
        const float* f1w = fc1_w + (size_t)l * 512 * 2048;
        const float* f1b = fc1_b + (size_t)l * 2048;
        const float* f2w = fc2_w + (size_t)l * 2048 * 512;
        const float* f2b = fc2_b + (size_t)l * 512;

        // LN1
        ln_kernel<<<4096, 128>>>(px, n1_g + l * 512, n1_b + l * 512, pln, 1e-5f);
        // QKV gemm: (4096x512)*(512x1536)
        sgemm_kernel<<<dim3(24, 64), 256>>>(pln, qw, qb, nullptr, pqkv, 4096, 1536, 512, 0);
        // split + q/k head LN (HEAD_D = 32)
        qkv_split_kernel<<<8192, 256>>>(pqkv, nq_g + l * 32, nq_b + l * 32,
                                        nk_g + l * 32, nk_b + l * 32, pq, pk, pv);
        // scores
        scores_kernel<<<dim3(16, 16, 64), 256>>>(pq, pk, ps);
        // softmax
        softmax_kernel<<<65536, 256>>>(ps);
        // attn @ V -> merged heads
        av_kernel<<<dim3(16, 64), 256>>>(ps, pv, po);
        // proj + residual
        sgemm_kernel<<<dim3(8, 64), 256>>>(po, pw, pb, px, px2, 4096, 512, 512, 1);
        // LN2
        ln_kernel<<<4096, 128>>>(px2, n2_g + l * 512, n2_b + l * 512, pln, 1e-5f);
        // fc1 + GELU
        sgemm_kernel<<<dim3(32, 64), 256>>>(pln, f1w, f1b, nullptr, pmlp, 4096, 2048, 512, 2);
        // fc2 + residual -> x
        sgemm_kernel<<<dim3(8, 64), 256>>>(pmlp, f2w, f2b, px2, px, 4096, 512, 2048, 1);
    }

    // final LN (no affine, eps 1e-6)
    ln_kernel<<<4096, 128>>>(px, nullptr, nullptr, pln, 1e-6f);
    // final linear: (4096x512)*(512x1024)
    sgemm_kernel<<<dim3(16, 64), 256>>>(pln, fin_w, fin_b, nullptr, pfin, 4096, 1024, 512, 0);
    // unpatchify
    unpatch_kernel<<<(4 * 64 * 128 * 128 + 255) / 256, 256>>>(pfin, pimg);
    // convs
    conv1_kernel<<<(4 * 16 * 128 * 128 + 255) / 256, 256>>>(pimg, c1_w, c1_b, pc1);
    conv2_kernel<<<(4 * 3 * 128 * 128 + 255) / 256, 256>>>(pc1, c2_w, c2_b, out);
}

// round 5
// speedup vs baseline: 1.1912x; 1.1912x over previous
#include <cuda_runtime.h>
#include <math.h>
#include <stdint.h>

// ---------------- scratch (static device globals; no allocations) ----------
__device__ float g_x   [4096*512];
__device__ float g_x2  [4096*512];
__device__ float g_ln  [4096*512];
__device__ float g_qkv [4096*1536];
__device__ float g_mlp [4096*2048];
__device__ float g_q   [64*1024*32];
__device__ float g_k   [64*1024*32];
__device__ float g_v   [64*1024*32];
__device__ float g_s   [64UL*1024*1024];   // 268 MB scores
__device__ float g_o   [4096*512];
__device__ float g_fin [4096*1024];
__device__ float g_img [4*64*128*128];
__device__ float g_c1  [4*16*128*128];

// ---------------- helpers --------------------------------------------------
__device__ __forceinline__ float to_tf32(float x) {
    uint32_t u;
    asm("cvt.rna.tf32.f32 %0, %1;" : "=r"(u) : "f"(x));
    return __uint_as_float(u);
}

__device__ __forceinline__ void mma_tf32(float* c, const uint32_t* a, const uint32_t* b) {
    asm volatile(
        "mma.sync.aligned.m16n8k8.row.col.f32.tf32.tf32.f32 "
        "{%0,%1,%2,%3}, {%4,%5,%6,%7}, {%8,%9}, {%0,%1,%2,%3};"
        : "+f"(c[0]), "+f"(c[1]), "+f"(c[2]), "+f"(c[3])
        : "r"(a[0]), "r"(a[1]), "r"(a[2]), "r"(a[3]), "r"(b[0]), "r"(b[1]));
}

// ---------------- pos-embed add -------------------------------------------
__global__ void add_pe_kernel(const float* __restrict__ x, float* __restrict__ out) {
    int idx = blockIdx.x * blockDim.x + threadIdx.x;
    if (idx >= 4 * 1024 * 512) return;
    int c = idx & 511;
    int p = (idx >> 9) & 1023;
    int i = p >> 5, j = p & 31;
    int pos = (c < 256) ? j : i;
    int cc = c & 255;
    int m = cc & 127;
    double om = pow(10000.0, -(double)m / 128.0);
    double a = (double)pos * om;
    float pe = (cc < 128) ? (float)sin(a) : (float)cos(a);
    out[idx] = x[idx] + pe;
}

// ---------------- layernorm over rows of 512 ------------------------------
__global__ void ln_kernel(const float* __restrict__ in, const float* __restrict__ g,
                          const float* __restrict__ b, float* __restrict__ out,
                          float eps) {
    int row = blockIdx.x;
    const float* x = in + (size_t)row * 512;
    int t = threadIdx.x;                       // 128 threads
    float v[4];
    float s = 0.f;
#pragma unroll
    for (int i = 0; i < 4; i++) { v[i] = x[t + i * 128]; s += v[i]; }
    __shared__ float red[128];
    red[t] = s; __syncthreads();
    for (int o = 64; o > 0; o >>= 1) { if (t < o) red[t] += red[t + o]; __syncthreads(); }
    float mu = red[0] * (1.f / 512.f);
    __syncthreads();
    float sq = 0.f;
#pragma unroll
    for (int i = 0; i < 4; i++) { float d = v[i] - mu; sq += d * d; }
    red[t] = sq; __syncthreads();
    for (int o = 64; o > 0; o >>= 1) { if (t < o) red[t] += red[t + o]; __syncthreads(); }
    float rstd = rsqrtf(red[0] * (1.f / 512.f) + eps);
#pragma unroll
    for (int i = 0; i < 4; i++) {
        int c = t + i * 128;
        float y = (v[i] - mu) * rstd;
        if (g) y = y * g[c] + b[c];
        out[(size_t)row * 512 + c] = y;
    }
}

// ---------------- tf32 tensor-core SGEMM ----------------------------------
// C = A(MxK) * B(KxN) + bias [mode 1: +res, mode 2: GELU]
// block: 256 thr, tile 128(M) x 64(N), Kblk 32. warps 4(M) x 2(N), warp tile 32x32.
__global__ void sgemm_tf32_kernel(const float* __restrict__ A, const float* __restrict__ B,
                                  const float* __restrict__ bias, const float* __restrict__ res,
                                  float* __restrict__ C, int M, int N, int K, int mode) {
    __shared__ float As[128][36];
    __shared__ float Bs[32][68];
    int tid = threadIdx.x;
    int w = tid >> 5, lane = tid & 31;
    int g = lane >> 2, tig = lane & 3;
    int warp_m = w & 3, warp_n = w >> 2;
    int bm = blockIdx.y * 128, bn = blockIdx.x * 64;

    float acc[2][4][4] = {};

    for (int k0 = 0; k0 < K; k0 += 32) {
        // fill A tile 128x32 (16 elems/thread), coalesced on k
#pragma unroll
        for (int i = 0; i < 16; i++) {
            int idx = tid + i * 256;
            int m = idx >> 5, kk = idx & 31;
            As[m][kk] = to_tf32(A[(size_t)(bm + m) * K + k0 + kk]);
        }
        // fill B tile 32x64 (8 elems/thread)
#pragma unroll
        for (int i = 0; i < 8; i++) {
            int idx = tid + i * 256;
            int kk = idx >> 6, n = idx & 63;
            Bs[kk][n] = to_tf32(B[(size_t)(k0 + kk) * N + bn + n]);
        }
        __syncthreads();
#pragma unroll
        for (int ks = 0; ks < 4; ks++) {
            int kk = ks * 8;
            uint32_t a[2][4], b[4][2];
#pragma unroll
            for (int mt = 0; mt < 2; mt++) {
                int mr = warp_m * 32 + mt * 16;
                a[mt][0] = __float_as_uint(As[mr + g][kk + tig]);
                a[mt][1] = __float_as_uint(As[mr + 8 + g][kk + tig]);
                a[mt][2] = __float_as_uint(As[mr + g][kk + 4 + tig]);
                a[mt][3] = __float_as_uint(As[mr + 8 + g][kk + 4 + tig]);
            }
#pragma unroll
            for (int nt = 0; nt < 4; nt++) {
                int nc = warp_n * 32 + nt * 8;
                b[nt][0] = __float_as_uint(Bs[kk + tig][nc + g]);
                b[nt][1] = __float_as_uint(Bs[kk + 4 + tig][nc + g]);
            }
#pragma unroll
            for (int mt = 0; mt < 2; mt++)
#pragma unroll
                for (int nt = 0; nt < 4; nt++)
                    mma_tf32(acc[mt][nt], a[mt], b[nt]);
        }
        __syncthreads();
    }

#pragma unroll
    for (int mt = 0; mt < 2; mt++) {
#pragma unroll
        for (int nt = 0; nt < 4; nt++) {
            int row0 = bm + warp_m * 32 + mt * 16 + g;
            int col0 = bn + warp_n * 32 + nt * 8 + 2 * tig;
#pragma unroll
            for (int i = 0; i < 4; i++) {
                int row = row0 + (i >> 1) * 8;
                int col = col0 + (i & 1);
                float v = acc[mt][nt][i] + bias[col];
                if (mode == 1) v += res[(size_t)row * N + col];
                else if (mode == 2) v = 0.5f * v * (1.f + erff(v * 0.70710678118654752f));
                C[(size_t)row * N + col] = v;
            }
        }
    }
}

// ---------------- qkv split to heads + q/k head-layernorm (HEAD_D = 32) ---
__global__ void qkv_split_kernel(const float* __restrict__ qkv,
                                 const float* __restrict__ nqg, const float* __restrict__ nqb,
                                 const float* __restrict__ nkg, const float* __restrict__ nkb,
                                 float* __restrict__ q, float* __restrict__ k,
                                 float* __restrict__ v) {
    int warp = (blockIdx.x * blockDim.x + threadIdx.x) >> 5;
    int lane = threadIdx.x & 31;
    if (warp >= 4096 * 16) return;
    int t = warp >> 4;
    int h = warp & 15;
    int b = t >> 10, n = t & 1023;
    const float* base = qkv + (size_t)t * 1536 + h * 32;
    float qv = base[lane];
    float kv = base[512 + lane];
    float vv = base[1024 + lane];

    float sq = qv, sk = kv;
#pragma unroll
    for (int o = 16; o > 0; o >>= 1) {
        sq += __shfl_xor_sync(0xffffffffu, sq, o);
        sk += __shfl_xor_sync(0xffffffffu, sk, o);
    }
    float mq = sq * (1.f / 32.f), mk = sk * (1.f / 32.f);
    float dq = qv - mq, dk = kv - mk;
    float vq = dq * dq, vk = dk * dk;
#pragma unroll
    for (int o = 16; o > 0; o >>= 1) {
        vq += __shfl_xor_sync(0xffffffffu, vq, o);
        vk += __shfl_xor_sync(0xffffffffu, vk, o);
    }
    float rq = rsqrtf(vq * (1.f / 32.f) + 1e-5f);
    float rk = rsqrtf(vk * (1.f / 32.f) + 1e-5f);
    size_t ob = ((size_t)(b * 16 + h) * 1024 + n) * 32;
    q[ob + lane] = dq * rq * nqg[lane] + nqb[lane];
    k[ob + lane] = dk * rk * nkg[lane] + nkb[lane];
    v[ob + lane] = vv;
}

// ---------------- scores (tf32 MMA): S = Q K^T / sqrt(32) -----------------
// block 256 thr, tile 64x64. warps: 2(M) x 4(N), warp tile 32x16 = 2x2 mma.
__global__ void scores_tf32_kernel(const float* __restrict__ q, const float* __restrict__ k,
                                   float* __restrict__ s) {
    int bh = blockIdx.z;
    int bm = blockIdx.y * 64, bn = blockIdx.x * 64;
    __shared__ float Qs[64][36];
    __shared__ float Ks[64][36];
    int tid = threadIdx.x;
    int w = tid >> 5, lane = tid & 31;
    int g = lane >> 2, tig = lane & 3;
    int warp_m = w & 1, warp_n = w >> 1;
    const float* qb = q + ((size_t)bh * 1024 + bm) * 32;
    const float* kb = k + ((size_t)bh * 1024 + bn) * 32;
#pragma unroll
    for (int i = 0; i < 8; i++) {
        int idx = tid + i * 256;
        int r = idx >> 5, c = idx & 31;
        Qs[r][c] = to_tf32(qb[r * 32 + c]);
        Ks[r][c] = to_tf32(kb[r * 32 + c]);
    }
    __syncthreads();

    float acc[2][2][4] = {};
#pragma unroll
    for (int ks = 0; ks < 4; ks++) {
        int kk = ks * 8;
        uint32_t a[2][4], b[2][2];
#pragma unroll
        for (int mt = 0; mt < 2; mt++) {
            int mr = warp_m * 32 + mt * 16;
            a[mt][0] = __float_as_uint(Qs[mr + g][kk + tig]);
            a[mt][1] = __float_as_uint(Qs[mr + 8 + g][kk + tig]);
            a[mt][2] = __float_as_uint(Qs[mr + g][kk + 4 + tig]);
            a[mt][3] = __float_as_uint(Qs[mr + 8 + g][kk + 4 + tig]);
        }
#pragma unroll
        for (int nt = 0; nt < 2; nt++) {
            int nc = warp_n * 16 + nt * 8;
            b[nt][0] = __float_as_uint(Ks[nc + g][kk + tig]);
            b[nt][1] = __float_as_uint(Ks[nc + g][kk + 4 + tig]);
        }
#pragma unroll
        for (int mt = 0; mt < 2; mt++)
#pragma unroll
            for (int nt = 0; nt < 2; nt++)
                mma_tf32(acc[mt][nt], a[mt], b[nt]);
    }

    const float sc = 0.17677669529663689f;   // 1/sqrt(32)
#pragma unroll
    for (int mt = 0; mt < 2; mt++)
#pragma unroll
        for (int nt = 0; nt < 2; nt++) {
            int row0 = bm + warp_m * 32 + mt * 16 + g;
            int col0 = bn + warp_n * 16 + nt * 8 + 2 * tig;
#pragma unroll
            for (int i = 0; i < 4; i++) {
                int row = row0 + (i >> 1) * 8;
                int col = col0 + (i & 1);
                s[((size_t)bh * 1024 + row) * 1024 + col] = acc[mt][nt][i] * sc;
            }
        }
}

// ---------------- row softmax over 1024 -----------------------------------
__global__ void softmax_kernel(float* __restrict__ s) {
    size_t row = blockIdx.x;
    float* p = s + row * 1024;
    int t = threadIdx.x;
    float v[4];
    float mx = -1e30f;
#pragma unroll
    for (int i = 0; i < 4; i++) { v[i] = p[t + i * 256]; mx = fmaxf(mx, v[i]); }
    __shared__ float red[256];
    red[t] = mx; __syncthreads();
    for (int o = 128; o > 0; o >>= 1) { if (t < o) red[t] = fmaxf(red[t], red[t + o]); __syncthreads(); }
    mx = red[0];
    __syncthreads();
    float sum = 0.f;
#pragma unroll
    for (int i = 0; i < 4; i++) { v[i] = expf(v[i] - mx); sum += v[i]; }
    red[t] = sum; __syncthreads();
    for (int o = 128; o > 0; o >>= 1) { if (t < o) red[t] += red[t + o]; __syncthreads(); }
    float inv = 1.f / red[0];
#pragma unroll
    for (int i = 0; i < 4; i++) p[t + i * 256] = v[i] * inv;
}

// ---------------- O = attn @ V (tf32 MMA), merged-head output -------------
// block 256 thr, tile 64(M rows) x 32(d). warps 4(M) x 2(N), warp tile 16x16.
__global__ void av_tf32_kernel(const float* __restrict__ s, const float* __restrict__ v,
                               float* __restrict__ o) {
    int bh = blockIdx.y;
    int bm = blockIdx.x * 64;
    int b = bh >> 4, h = bh & 15;
    __shared__ float Ss[64][68];
    __shared__ float Vs[64][36];
    int tid = threadIdx.x;
    int w = tid >> 5, lane = tid & 31;
    int g = lane >> 2, tig = lane & 3;
    int warp_m = w & 3, warp_n = w >> 2;

    float acc[2][4] = {};
    for (int k0 = 0; k0 < 1024; k0 += 64) {
#pragma unroll
        for (int i = 0; i < 16; i++) {
            int idx = tid + i * 256;
            int r = idx >> 6, c = idx & 63;
            Ss[r][c] = to_tf32(s[((size_t)bh * 1024 + bm + r) * 1024 + k0 + c]);
        }
#pragma unroll
        for (int i = 0; i < 8; i++) {
            int idx = tid + i * 256;
            int r = idx >> 5, c = idx & 31;
            Vs[r][c] = to_tf32(v[((size_t)bh * 1024 + k0 + r) * 32 + c]);
        }
        __syncthreads();
#pragma unroll
        for (int ks = 0; ks < 8; ks++) {
            int kk = ks * 8;
            uint32_t a[4], bb[2][2];
            int mr = warp_m * 16;
            a[0] = __float_as_uint(Ss[mr + g][kk + tig]);
            a[1] = __float_as_uint(Ss[mr + 8 + g][kk + tig]);
            a[2] = __float_as_uint(Ss[mr + g][kk + 4 + tig]);
            a[3] = __float_as_uint(Ss[mr + 8 + g][kk + 4 + tig]);
#pragma unroll
            for (int nt = 0; nt < 2; nt++) {
                int nc = warp_n * 16 + nt * 8;
                bb[nt][0] = __float_as_uint(Vs[kk + tig][nc + g]);
                bb[nt][1] = __float_as_uint(Vs[kk + 4 + tig][nc + g]);
            }
#pragma unroll
            for (int nt = 0; nt < 2; nt++)
                mma_tf32(acc[nt], a, bb[nt]);
        }
        __syncthreads();
    }

#pragma unroll
    for (int nt = 0; nt < 2; nt++) {
        int row0 = bm + warp_m * 16 + g;
        int col0 = warp_n * 16 + nt * 8 + 2 * tig;
#pragma unroll
        for (int i = 0; i < 4; i++) {
            int n = row0 + (i >> 1) * 8;
            int d = col0 + (i & 1);
            o[((size_t)(b * 1024 + n)) * 512 + h * 32 + d] = acc[nt][i];
        }
    }
}

// ---------------- unpatchify ----------------------------------------------
__global__ void unpatch_kernel(const float* __restrict__ fin, float* __restrict__ img) {
    int idx = blockIdx.x * blockDim.x + threadIdx.x;
    if (idx >= 4 * 64 * 128 * 128) return;
    int W = idx & 127;
    int H = (idx >> 7) & 127;
    int c = (idx >> 14) & 63;
    int b = idx >> 20;
    int hh = H >> 2, p = H & 3, ww = W >> 2, qq = W & 3;
    img[idx] = fin[((size_t)(b * 1024 + hh * 32 + ww)) * 1024 + c * 16 + p * 4 + qq];
}

// ---------------- direct 3x3 convs ----------------------------------------
__global__ void conv1_kernel(const float* __restrict__ img, const float* __restrict__ w,
                             const float* __restrict__ bias, float* __restrict__ out) {
    int idx = blockIdx.x * blockDim.x + threadIdx.x;
    if (idx >= 4 * 16 * 128 * 128) return;
    int x = idx & 127, y = (idx >> 7) & 127, oc = (idx >> 14) & 15, b = idx >> 18;
    float acc = bias[oc];
    for (int ic = 0; ic < 64; ic++) {
        const float* ip = img + ((size_t)(b * 64 + ic)) * 16384;
        const float* wp = w + (size_t)(oc * 64 + ic) * 9;
#pragma unroll
        for (int ky = 0; ky < 3; ky++) {
            int yy = y + ky - 1;
            if (yy < 0 || yy > 127) continue;
#pragma unroll
            for (int kx = 0; kx < 3; kx++) {
                int xx = x + kx - 1;
                if (xx < 0 || xx > 127) continue;
                acc += ip[yy * 128 + xx] * wp[ky * 3 + kx];
            }
        }
    }
    out[idx] = fmaxf(acc, 0.f);
}

__global__ void conv2_kernel(const float* __restrict__ img, const float* __restrict__ w,
                             const float* __restrict__ bias, float* __restrict__ out) {
    int idx = blockIdx.x * blockDim.x + threadIdx.x;
    if (idx >= 4 * 3 * 128 * 128) return;
    int x = idx & 127, y = (idx >> 7) & 127;
    int oc = (idx >> 14) % 3, b = idx / (3 * 16384);
    float acc = bias[oc];
    for (int ic = 0; ic < 16; ic++) {
        const float* ip = img + ((size_t)(b * 16 + ic)) * 16384;
        const float* wp = w + (size_t)(oc * 16 + ic) * 9;
#pragma unroll
        for (int ky = 0; ky < 3; ky++) {
            int yy = y + ky - 1;
            if (yy < 0 || yy > 127) continue;
#pragma unroll
            for (int kx = 0; kx < 3; kx++) {
                int xx = x + kx - 1;
                if (xx < 0 || xx > 127) continue;
                acc += ip[yy * 128 + xx] * wp[ky * 3 + kx];
            }
        }
    }
    out[idx] = acc;
}

// ---------------- driver ---------------------------------------------------
extern "C" void kernel_launch(void* const* d_in, const int* in_sizes, int n_in,
                              void* d_out, int out_size) {
    const float* x_in  = (const float*)d_in[0];
    const float* qkv_w = (const float*)d_in[1];
    const float* qkv_b = (const float*)d_in[2];
    const float* proj_w= (const float*)d_in[3];
    const float* proj_b= (const float*)d_in[4];
    const float* nq_g  = (const float*)d_in[5];
    const float* nq_b  = (const float*)d_in[6];
    const float* nk_g  = (const float*)d_in[7];
    const float* nk_b  = (const float*)d_in[8];
    const float* n1_g  = (const float*)d_in[9];
    const float* n1_b  = (const float*)d_in[10];
    const float* n2_g  = (const float*)d_in[11];
    const float* n2_b  = (const float*)d_in[12];
    const float* fc1_w = (const float*)d_in[13];
    const float* fc1_b = (const float*)d_in[14];
    const float* fc2_w = (const float*)d_in[15];
    const float* fc2_b = (const float*)d_in[16];
    const float* fin_w = (const float*)d_in[17];
    const float* fin_b = (const float*)d_in[18];
    const float* c1_w  = (const float*)d_in[19];
    const float* c1_b  = (const float*)d_in[20];
    const float* c2_w  = (const float*)d_in[21];
    const float* c2_b  = (const float*)d_in[22];
    float* out = (float*)d_out;

    float *px, *px2, *pln, *pqkv, *pmlp, *pq, *pk, *pv, *ps, *po, *pfin, *pimg, *pc1;
    cudaGetSymbolAddress((void**)&px,   g_x);
    cudaGetSymbolAddress((void**)&px2,  g_x2);
    cudaGetSymbolAddress((void**)&pln,  g_ln);
    cudaGetSymbolAddress((void**)&pqkv, g_qkv);
    cudaGetSymbolAddress((void**)&pmlp, g_mlp);
    cudaGetSymbolAddress((void**)&pq,   g_q);
    cudaGetSymbolAddress((void**)&pk,   g_k);
    cudaGetSymbolAddress((void**)&pv,   g_v);
    cudaGetSymbolAddress((void**)&ps,   g_s);
    cudaGetSymbolAddress((void**)&po,   g_o);
    cudaGetSymbolAddress((void**)&pfin, g_fin);
    cudaGetSymbolAddress((void**)&pimg, g_img);
    cudaGetSymbolAddress((void**)&pc1,  g_c1);

    add_pe_kernel<<<(4 * 1024 * 512 + 255) / 256, 256>>>(x_in, px);

    for (int l = 0; l < 8; l++) {
        const float* qw = qkv_w + (size_t)l * 512 * 1536;
        const float* qb = qkv_b + (size_t)l * 1536;
        const float* pw = proj_w + (size_t)l * 512 * 512;
        const float* pb = proj_b + (size_t)l * 512;
        const float* f1w = fc1_w + (size_t)l * 512 * 2048;
        const float* f1b = fc1_b + (size_t)l * 2048;
        const float* f2w = fc2_w + (size_t)l * 2048 * 512;
        const float* f2b = fc2_b + (size_t)l * 512;

        // LN1
        ln_kernel<<<4096, 128>>>(px, n1_g + l * 512, n1_b + l * 512, pln, 1e-5f);
        // QKV gemm: (4096x512)*(512x1536)
        sgemm_tf32_kernel<<<dim3(24, 32), 256>>>(pln, qw, qb, nullptr, pqkv, 4096, 1536, 512, 0);
        // split + q/k head LN (HEAD_D = 32)
        qkv_split_kernel<<<8192, 256>>>(pqkv, nq_g + l * 32, nq_b + l * 32,
                                        nk_g + l * 32, nk_b + l * 32, pq, pk, pv);
        // scores (tensor core)
        scores_tf32_kernel<<<dim3(16, 16, 64), 256>>>(pq, pk, ps);
        // softmax
        softmax_kernel<<<65536, 256>>>(ps);
        // attn @ V -> merged heads (tensor core)
        av_tf32_kernel<<<dim3(16, 64), 256>>>(ps, pv, po);
        // proj + residual
        sgemm_tf32_kernel<<<dim3(8, 32), 256>>>(po, pw, pb, px, px2, 4096, 512, 512, 1);
        // LN2
        ln_kernel<<<4096, 128>>>(px2, n2_g + l * 512, n2_b + l * 512, pln, 1e-5f);
        // fc1 + GELU
        sgemm_tf32_kernel<<<dim3(32, 32), 256>>>(pln, f1w, f1b, nullptr, pmlp, 4096, 2048, 512, 2);
        // fc2 + residual -> x
        sgemm_tf32_kernel<<<dim3(8, 32), 256>>>(pmlp, f2w, f2b, px2, px, 4096, 512, 2048, 1);
    }

    // final LN (no affine, eps 1e-6)
    ln_kernel<<<4096, 128>>>(px, nullptr, nullptr, pln, 1e-6f);
    // final linear: (4096x512)*(512x1024)
    sgemm_tf32_kernel<<<dim3(16, 32), 256>>>(pln, fin_w, fin_b, nullptr, pfin, 4096, 1024, 512, 0);
    // unpatchify
    unpatch_kernel<<<(4 * 64 * 128 * 128 + 255) / 256, 256>>>(pfin, pimg);
    // convs
    conv1_kernel<<<(4 * 16 * 128 * 128 + 255) / 256, 256>>>(pimg, c1_w, c1_b, pc1);
    conv2_kernel<<<(4 * 3 * 128 * 128 + 255) / 256, 256>>>(pc1, c2_w, c2_b, out);
}

// round 6
// speedup vs baseline: 3.2410x; 2.7208x over previous
#include <cuda_runtime.h>
#include <math.h>
#include <stdint.h>

// ---------------- scratch (static device globals; no allocations) ----------
__device__ float g_x   [4096*512];
__device__ float g_x2  [4096*512];
__device__ float g_ln  [4096*512];
__device__ float g_qkv [4096*1536];
__device__ float g_mlp [4096*2048];
__device__ float g_q   [64*1024*32];
__device__ float g_k   [64*1024*32];
__device__ float g_v   [64*1024*32];
__device__ float g_o   [4096*512];
__device__ float g_fin [4096*1024];
__device__ float g_img [4*64*128*128];
__device__ float g_c1  [4*16*128*128];

// ---------------- helpers --------------------------------------------------
__device__ __forceinline__ float to_tf32(float x) {
    uint32_t u;
    asm("cvt.rna.tf32.f32 %0, %1;" : "=r"(u) : "f"(x));
    return __uint_as_float(u);
}

__device__ __forceinline__ void mma_tf32(float* c, const uint32_t* a, const uint32_t* b) {
    asm volatile(
        "mma.sync.aligned.m16n8k8.row.col.f32.tf32.tf32.f32 "
        "{%0,%1,%2,%3}, {%4,%5,%6,%7}, {%8,%9}, {%0,%1,%2,%3};"
        : "+f"(c[0]), "+f"(c[1]), "+f"(c[2]), "+f"(c[3])
        : "r"(a[0]), "r"(a[1]), "r"(a[2]), "r"(a[3]), "r"(b[0]), "r"(b[1]));
}

// ---------------- pos-embed add -------------------------------------------
__global__ void add_pe_kernel(const float* __restrict__ x, float* __restrict__ out) {
    int idx = blockIdx.x * blockDim.x + threadIdx.x;
    if (idx >= 4 * 1024 * 512) return;
    int c = idx & 511;
    int p = (idx >> 9) & 1023;
    int i = p >> 5, j = p & 31;
    int pos = (c < 256) ? j : i;
    int cc = c & 255;
    int m = cc & 127;
    double om = pow(10000.0, -(double)m / 128.0);
    double a = (double)pos * om;
    float pe = (cc < 128) ? (float)sin(a) : (float)cos(a);
    out[idx] = x[idx] + pe;
}

// ---------------- layernorm over rows of 512 ------------------------------
__global__ void ln_kernel(const float* __restrict__ in, const float* __restrict__ g,
                          const float* __restrict__ b, float* __restrict__ out,
                          float eps) {
    int row = blockIdx.x;
    const float* x = in + (size_t)row * 512;
    int t = threadIdx.x;                       // 128 threads
    float v[4];
    float s = 0.f;
#pragma unroll
    for (int i = 0; i < 4; i++) { v[i] = x[t + i * 128]; s += v[i]; }
    __shared__ float red[128];
    red[t] = s; __syncthreads();
    for (int o = 64; o > 0; o >>= 1) { if (t < o) red[t] += red[t + o]; __syncthreads(); }
    float mu = red[0] * (1.f / 512.f);
    __syncthreads();
    float sq = 0.f;
#pragma unroll
    for (int i = 0; i < 4; i++) { float d = v[i] - mu; sq += d * d; }
    red[t] = sq; __syncthreads();
    for (int o = 64; o > 0; o >>= 1) { if (t < o) red[t] += red[t + o]; __syncthreads(); }
    float rstd = rsqrtf(red[0] * (1.f / 512.f) + eps);
#pragma unroll
    for (int i = 0; i < 4; i++) {
        int c = t + i * 128;
        float y = (v[i] - mu) * rstd;
        if (g) y = y * g[c] + b[c];
        out[(size_t)row * 512 + c] = y;
    }
}

// ---------------- tf32 tensor-core SGEMM v2 --------------------------------
// C = A(MxK)*B(KxN)+bias [mode1:+res, mode2:GELU]. 256 thr, tile 128x128, Kblk 32.
// warps 2(M)x4(N), warp tile 64x32 = 4x4 mma tiles.
__global__ void sgemm_tf32_kernel(const float* __restrict__ A, const float* __restrict__ B,
                                  const float* __restrict__ bias, const float* __restrict__ res,
                                  float* __restrict__ C, int M, int N, int K, int mode) {
    __shared__ float As[128][36];    // stride 36 == 4 mod 32 (g-indexed rows)
    __shared__ float Bs[32][136];    // stride 136 == 8 mod 32 (tig-indexed rows)
    int tid = threadIdx.x;
    int w = tid >> 5, lane = tid & 31;
    int g = lane >> 2, tig = lane & 3;
    int warp_m = w & 1, warp_n = w >> 1;
    int bm = blockIdx.y * 128, bn = blockIdx.x * 128;

    float acc[4][4][4] = {};
    float4 pa[4], pb[4];

#pragma unroll
    for (int i = 0; i < 4; i++) {
        int idx = i * 256 + tid;
        int row = idx >> 3, kv = idx & 7;
        pa[i] = *(const float4*)&A[(size_t)(bm + row) * K + kv * 4];
        int kk = idx >> 5, nv = idx & 31;
        pb[i] = *(const float4*)&B[(size_t)kk * N + bn + nv * 4];
    }

    for (int k0 = 0; k0 < K; k0 += 32) {
#pragma unroll
        for (int i = 0; i < 4; i++) {
            int idx = i * 256 + tid;
            int row = idx >> 3, kv = idx & 7;
            float4 t = pa[i];
            float4 tc = make_float4(to_tf32(t.x), to_tf32(t.y), to_tf32(t.z), to_tf32(t.w));
            *(float4*)&As[row][kv * 4] = tc;
            int kk = idx >> 5, nv = idx & 31;
            float4 u = pb[i];
            float4 uc = make_float4(to_tf32(u.x), to_tf32(u.y), to_tf32(u.z), to_tf32(u.w));
            *(float4*)&Bs[kk][nv * 4] = uc;
        }
        __syncthreads();
        if (k0 + 32 < K) {
#pragma unroll
            for (int i = 0; i < 4; i++) {
                int idx = i * 256 + tid;
                int row = idx >> 3, kv = idx & 7;
                pa[i] = *(const float4*)&A[(size_t)(bm + row) * K + k0 + 32 + kv * 4];
                int kk = idx >> 5, nv = idx & 31;
                pb[i] = *(const float4*)&B[(size_t)(k0 + 32 + kk) * N + bn + nv * 4];
            }
        }
#pragma unroll
        for (int ks = 0; ks < 4; ks++) {
            int kk = ks * 8;
            uint32_t a[4][4], b[4][2];
#pragma unroll
            for (int mt = 0; mt < 4; mt++) {
                int mr = warp_m * 64 + mt * 16;
                a[mt][0] = __float_as_uint(As[mr + g][kk + tig]);
                a[mt][1] = __float_as_uint(As[mr + 8 + g][kk + tig]);
                a[mt][2] = __float_as_uint(As[mr + g][kk + 4 + tig]);
                a[mt][3] = __float_as_uint(As[mr + 8 + g][kk + 4 + tig]);
            }
#pragma unroll
            for (int nt = 0; nt < 4; nt++) {
                int nc = warp_n * 32 + nt * 8;
                b[nt][0] = __float_as_uint(Bs[kk + tig][nc + g]);
                b[nt][1] = __float_as_uint(Bs[kk + 4 + tig][nc + g]);
            }
#pragma unroll
            for (int mt = 0; mt < 4; mt++)
#pragma unroll
                for (int nt = 0; nt < 4; nt++)
                    mma_tf32(acc[mt][nt], a[mt], b[nt]);
        }
        __syncthreads();
    }

#pragma unroll
    for (int mt = 0; mt < 4; mt++) {
#pragma unroll
        for (int nt = 0; nt < 4; nt++) {
            int row0 = bm + warp_m * 64 + mt * 16 + g;
            int col0 = bn + warp_n * 32 + nt * 8 + 2 * tig;
#pragma unroll
            for (int i = 0; i < 4; i++) {
                int row = row0 + (i >> 1) * 8;
                int col = col0 + (i & 1);
                float v = acc[mt][nt][i] + bias[col];
                if (mode == 1) v += res[(size_t)row * N + col];
                else if (mode == 2) v = 0.5f * v * (1.f + erff(v * 0.70710678118654752f));
                C[(size_t)row * N + col] = v;
            }
        }
    }
}

// ---------------- qkv split + q/k head-LN (HEAD_D=32); q pre-scaled -------
__global__ void qkv_split_kernel(const float* __restrict__ qkv,
                                 const float* __restrict__ nqg, const float* __restrict__ nqb,
                                 const float* __restrict__ nkg, const float* __restrict__ nkb,
                                 float* __restrict__ q, float* __restrict__ k,
                                 float* __restrict__ v) {
    int warp = (blockIdx.x * blockDim.x + threadIdx.x) >> 5;
    int lane = threadIdx.x & 31;
    if (warp >= 4096 * 16) return;
    int t = warp >> 4;
    int h = warp & 15;
    int b = t >> 10, n = t & 1023;
    const float* base = qkv + (size_t)t * 1536 + h * 32;
    float qv = base[lane];
    float kv = base[512 + lane];
    float vv = base[1024 + lane];

    float sq = qv, sk = kv;
#pragma unroll
    for (int o = 16; o > 0; o >>= 1) {
        sq += __shfl_xor_sync(0xffffffffu, sq, o);
        sk += __shfl_xor_sync(0xffffffffu, sk, o);
    }
    float mq = sq * (1.f / 32.f), mk = sk * (1.f / 32.f);
    float dq = qv - mq, dk = kv - mk;
    float vq = dq * dq, vk = dk * dk;
#pragma unroll
    for (int o = 16; o > 0; o >>= 1) {
        vq += __shfl_xor_sync(0xffffffffu, vq, o);
        vk += __shfl_xor_sync(0xffffffffu, vk, o);
    }
    float rq = rsqrtf(vq * (1.f / 32.f) + 1e-5f);
    float rk = rsqrtf(vk * (1.f / 32.f) + 1e-5f);
    const float sc = 0.17677669529663689f;   // 1/sqrt(32), folded into q
    size_t ob = ((size_t)(b * 16 + h) * 1024 + n) * 32;
    q[ob + lane] = (dq * rq * nqg[lane] + nqb[lane]) * sc;
    k[ob + lane] = dk * rk * nkg[lane] + nkb[lane];
    v[ob + lane] = vv;
}

// ---------------- flash attention: S=QK^T, online softmax, O=P@V ----------
// grid (8 qblocks, 64 bh), 256 thr. Each warp owns 16 q rows. 64-key tiles.
__global__ void flash_kernel(const float* __restrict__ q, const float* __restrict__ k,
                             const float* __restrict__ v, float* __restrict__ o) {
    extern __shared__ float sm[];
    float* Qs = sm;                      // 128 x 36
    float* Ks = Qs + 128 * 36;           // 64 x 36  (g-indexed rows)
    float* Vs = Ks + 64 * 36;            // 64 x 40  (tig-indexed rows)
    float* Ps = Vs + 64 * 40;            // 8 warps x 16 x 68

    int bh = blockIdx.y;
    int bm = blockIdx.x * 128;
    int b = bh >> 4, h = bh & 15;
    int tid = threadIdx.x;
    int w = tid >> 5, lane = tid & 31;
    int g = lane >> 2, tig = lane & 3;

    const float* qb = q + ((size_t)bh * 1024 + bm) * 32;
    const float* kb = k + (size_t)bh * 1024 * 32;
    const float* vb = v + (size_t)bh * 1024 * 32;

    // load Q tile (128x32) -> smem (tf32)
#pragma unroll
    for (int i = 0; i < 4; i++) {
        int idx = i * 256 + tid;
        int r = idx >> 3, dv = idx & 7;
        float4 t = *(const float4*)&qb[r * 32 + dv * 4];
        float* dst = &Qs[r * 36 + dv * 4];
        dst[0] = to_tf32(t.x); dst[1] = to_tf32(t.y);
        dst[2] = to_tf32(t.z); dst[3] = to_tf32(t.w);
    }
    __syncthreads();

    // Q fragments (persistent)
    uint32_t qa[4][4];
    int wr = w * 16;
#pragma unroll
    for (int ks = 0; ks < 4; ks++) {
        int kk = ks * 8;
        qa[ks][0] = __float_as_uint(Qs[(wr + g) * 36 + kk + tig]);
        qa[ks][1] = __float_as_uint(Qs[(wr + 8 + g) * 36 + kk + tig]);
        qa[ks][2] = __float_as_uint(Qs[(wr + g) * 36 + kk + 4 + tig]);
        qa[ks][3] = __float_as_uint(Qs[(wr + 8 + g) * 36 + kk + 4 + tig]);
    }

    float oacc[4][4] = {};
    float m0 = -1e30f, m1 = -1e30f, l0 = 0.f, l1 = 0.f;
    float* Pw = Ps + w * 16 * 68;

    for (int j = 0; j < 16; j++) {
        __syncthreads();   // protect Ks/Vs vs previous iteration's reads
        // load K,V tiles (64x32 each) -> smem (tf32)
#pragma unroll
        for (int i = 0; i < 2; i++) {
            int idx = i * 256 + tid;
            int r = idx >> 3, dv = idx & 7;
            float4 t = *(const float4*)&kb[(size_t)(j * 64 + r) * 32 + dv * 4];
            float* dk = &Ks[r * 36 + dv * 4];
            dk[0] = to_tf32(t.x); dk[1] = to_tf32(t.y);
            dk[2] = to_tf32(t.z); dk[3] = to_tf32(t.w);
            float4 u = *(const float4*)&vb[(size_t)(j * 64 + r) * 32 + dv * 4];
            float* dp = &Vs[r * 40 + dv * 4];
            dp[0] = to_tf32(u.x); dp[1] = to_tf32(u.y);
            dp[2] = to_tf32(u.z); dp[3] = to_tf32(u.w);
        }
        __syncthreads();

        // S = Q K^T : warp computes 16x64
        float s[8][4] = {};
#pragma unroll
        for (int ks = 0; ks < 4; ks++) {
            int kk = ks * 8;
            uint32_t bf[8][2];
#pragma unroll
            for (int nt = 0; nt < 8; nt++) {
                int nc = nt * 8;
                bf[nt][0] = __float_as_uint(Ks[(nc + g) * 36 + kk + tig]);
                bf[nt][1] = __float_as_uint(Ks[(nc + g) * 36 + kk + 4 + tig]);
            }
#pragma unroll
            for (int nt = 0; nt < 8; nt++)
                mma_tf32(s[nt], qa[ks], bf[nt]);
        }

        // online softmax (rows g and g+8)
        float rm0 = -1e30f, rm1 = -1e30f;
#pragma unroll
        for (int nt = 0; nt < 8; nt++) {
            rm0 = fmaxf(rm0, fmaxf(s[nt][0], s[nt][1]));
            rm1 = fmaxf(rm1, fmaxf(s[nt][2], s[nt][3]));
        }
        rm0 = fmaxf(rm0, __shfl_xor_sync(0xffffffffu, rm0, 1));
        rm0 = fmaxf(rm0, __shfl_xor_sync(0xffffffffu, rm0, 2));
        rm1 = fmaxf(rm1, __shfl_xor_sync(0xffffffffu, rm1, 1));
        rm1 = fmaxf(rm1, __shfl_xor_sync(0xffffffffu, rm1, 2));
        float nm0 = fmaxf(m0, rm0), nm1 = fmaxf(m1, rm1);
        float al0 = expf(m0 - nm0), al1 = expf(m1 - nm1);
        float rs0 = 0.f, rs1 = 0.f;
#pragma unroll
        for (int nt = 0; nt < 8; nt++) {
            s[nt][0] = expf(s[nt][0] - nm0);
            s[nt][1] = expf(s[nt][1] - nm0);
            s[nt][2] = expf(s[nt][2] - nm1);
            s[nt][3] = expf(s[nt][3] - nm1);
            rs0 += s[nt][0] + s[nt][1];
            rs1 += s[nt][2] + s[nt][3];
        }
        rs0 += __shfl_xor_sync(0xffffffffu, rs0, 1);
        rs0 += __shfl_xor_sync(0xffffffffu, rs0, 2);
        rs1 += __shfl_xor_sync(0xffffffffu, rs1, 1);
        rs1 += __shfl_xor_sync(0xffffffffu, rs1, 2);
        l0 = l0 * al0 + rs0;
        l1 = l1 * al1 + rs1;
        m0 = nm0; m1 = nm1;
#pragma unroll
        for (int nt = 0; nt < 4; nt++) {
            oacc[nt][0] *= al0; oacc[nt][1] *= al0;
            oacc[nt][2] *= al1; oacc[nt][3] *= al1;
        }

        // store P (tf32) to per-warp smem
#pragma unroll
        for (int nt = 0; nt < 8; nt++) {
            int nc = nt * 8 + 2 * tig;
            Pw[g * 68 + nc]           = to_tf32(s[nt][0]);
            Pw[g * 68 + nc + 1]       = to_tf32(s[nt][1]);
            Pw[(8 + g) * 68 + nc]     = to_tf32(s[nt][2]);
            Pw[(8 + g) * 68 + nc + 1] = to_tf32(s[nt][3]);
        }
        __syncwarp();

        // O += P @ V  (warp 16x32)
#pragma unroll
        for (int ks2 = 0; ks2 < 8; ks2++) {
            int kk = ks2 * 8;
            uint32_t a[4];
            a[0] = __float_as_uint(Pw[g * 68 + kk + tig]);
            a[1] = __float_as_uint(Pw[(8 + g) * 68 + kk + tig]);
            a[2] = __float_as_uint(Pw[g * 68 + kk + 4 + tig]);
            a[3] = __float_as_uint(Pw[(8 + g) * 68 + kk + 4 + tig]);
            uint32_t bf[4][2];
#pragma unroll
            for (int nt = 0; nt < 4; nt++) {
                int nc = nt * 8;
                bf[nt][0] = __float_as_uint(Vs[(kk + tig) * 40 + nc + g]);
                bf[nt][1] = __float_as_uint(Vs[(kk + 4 + tig) * 40 + nc + g]);
            }
#pragma unroll
            for (int nt = 0; nt < 4; nt++)
                mma_tf32(oacc[nt], a, bf[nt]);
        }
    }

    float il0 = 1.f / l0, il1 = 1.f / l1;
    int n0 = bm + w * 16 + g;
#pragma unroll
    for (int nt = 0; nt < 4; nt++) {
        int col = h * 32 + nt * 8 + 2 * tig;
        o[((size_t)(b * 1024 + n0)) * 512 + col]     = oacc[nt][0] * il0;
        o[((size_t)(b * 1024 + n0)) * 512 + col + 1] = oacc[nt][1] * il0;
        o[((size_t)(b * 1024 + n0 + 8)) * 512 + col]     = oacc[nt][2] * il1;
        o[((size_t)(b * 1024 + n0 + 8)) * 512 + col + 1] = oacc[nt][3] * il1;
    }
}

// ---------------- unpatchify ----------------------------------------------
__global__ void unpatch_kernel(const float* __restrict__ fin, float* __restrict__ img) {
    int idx = blockIdx.x * blockDim.x + threadIdx.x;
    if (idx >= 4 * 64 * 128 * 128) return;
    int W = idx & 127;
    int H = (idx >> 7) & 127;
    int c = (idx >> 14) & 63;
    int b = idx >> 20;
    int hh = H >> 2, p = H & 3, ww = W >> 2, qq = W & 3;
    img[idx] = fin[((size_t)(b * 1024 + hh * 32 + ww)) * 1024 + c * 16 + p * 4 + qq];
}

// ---------------- direct 3x3 convs ----------------------------------------
__global__ void conv1_kernel(const float* __restrict__ img, const float* __restrict__ w,
                             const float* __restrict__ bias, float* __restrict__ out) {
    int idx = blockIdx.x * blockDim.x + threadIdx.x;
    if (idx >= 4 * 16 * 128 * 128) return;
    int x = idx & 127, y = (idx >> 7) & 127, oc = (idx >> 14) & 15, b = idx >> 18;
    float acc = bias[oc];
    for (int ic = 0; ic < 64; ic++) {
        const float* ip = img + ((size_t)(b * 64 + ic)) * 16384;
        const float* wp = w + (size_t)(oc * 64 + ic) * 9;
#pragma unroll
        for (int ky = 0; ky < 3; ky++) {
            int yy = y + ky - 1;
            if (yy < 0 || yy > 127) continue;
#pragma unroll
            for (int kx = 0; kx < 3; kx++) {
                int xx = x + kx - 1;
                if (xx < 0 || xx > 127) continue;
                acc += ip[yy * 128 + xx] * wp[ky * 3 + kx];
            }
        }
    }
    out[idx] = fmaxf(acc, 0.f);
}

__global__ void conv2_kernel(const float* __restrict__ img, const float* __restrict__ w,
                             const float* __restrict__ bias, float* __restrict__ out) {
    int idx = blockIdx.x * blockDim.x + threadIdx.x;
    if (idx >= 4 * 3 * 128 * 128) return;
    int x = idx & 127, y = (idx >> 7) & 127;
    int oc = (idx >> 14) % 3, b = idx / (3 * 16384);
    float acc = bias[oc];
    for (int ic = 0; ic < 16; ic++) {
        const float* ip = img + ((size_t)(b * 16 + ic)) * 16384;
        const float* wp = w + (size_t)(oc * 16 + ic) * 9;
#pragma unroll
        for (int ky = 0; ky < 3; ky++) {
            int yy = y + ky - 1;
            if (yy < 0 || yy > 127) continue;
#pragma unroll
            for (int kx = 0; kx < 3; kx++) {
                int xx = x + kx - 1;
                if (xx < 0 || xx > 127) continue;
                acc += ip[yy * 128 + xx] * wp[ky * 3 + kx];
            }
        }
    }
    out[idx] = acc;
}

// ---------------- driver ---------------------------------------------------
extern "C" void kernel_launch(void* const* d_in, const int* in_sizes, int n_in,
                              void* d_out, int out_size) {
    const float* x_in  = (const float*)d_in[0];
    const float* qkv_w = (const float*)d_in[1];
    const float* qkv_b = (const float*)d_in[2];
    const float* proj_w= (const float*)d_in[3];
    const float* proj_b= (const float*)d_in[4];
    const float* nq_g  = (const float*)d_in[5];
    const float* nq_b  = (const float*)d_in[6];
    const float* nk_g  = (const float*)d_in[7];
    const float* nk_b  = (const float*)d_in[8];
    const float* n1_g  = (const float*)d_in[9];
    const float* n1_b  = (const float*)d_in[10];
    const float* n2_g  = (const float*)d_in[11];
    const float* n2_b  = (const float*)d_in[12];
    const float* fc1_w = (const float*)d_in[13];
    const float* fc1_b = (const float*)d_in[14];
    const float* fc2_w = (const float*)d_in[15];
    const float* fc2_b = (const float*)d_in[16];
    const float* fin_w = (const float*)d_in[17];
    const float* fin_b = (const float*)d_in[18];
    const float* c1_w  = (const float*)d_in[19];
    const float* c1_b  = (const float*)d_in[20];
    const float* c2_w  = (const float*)d_in[21];
    const float* c2_b  = (const float*)d_in[22];
    float* out = (float*)d_out;

    float *px, *px2, *pln, *pqkv, *pmlp, *pq, *pk, *pv, *po, *pfin, *pimg, *pc1;
    cudaGetSymbolAddress((void**)&px,   g_x);
    cudaGetSymbolAddress((void**)&px2,  g_x2);
    cudaGetSymbolAddress((void**)&pln,  g_ln);
    cudaGetSymbolAddress((void**)&pqkv, g_qkv);
    cudaGetSymbolAddress((void**)&pmlp, g_mlp);
    cudaGetSymbolAddress((void**)&pq,   g_q);
    cudaGetSymbolAddress((void**)&pk,   g_k);
    cudaGetSymbolAddress((void**)&pv,   g_v);
    cudaGetSymbolAddress((void**)&po,   g_o);
    cudaGetSymbolAddress((void**)&pfin, g_fin);
    cudaGetSymbolAddress((void**)&pimg, g_img);
    cudaGetSymbolAddress((void**)&pc1,  g_c1);

    const int FLASH_SMEM = (128 * 36 + 64 * 36 + 64 * 40 + 8 * 16 * 68) * 4;
    cudaFuncSetAttribute(flash_kernel, cudaFuncAttributeMaxDynamicSharedMemorySize, FLASH_SMEM);

    add_pe_kernel<<<(4 * 1024 * 512 + 255) / 256, 256>>>(x_in, px);

    for (int l = 0; l < 8; l++) {
        const float* qw = qkv_w + (size_t)l * 512 * 1536;
        const float* qb = qkv_b + (size_t)l * 1536;
        const float* pw = proj_w + (size_t)l * 512 * 512;
        const float* pb = proj_b + (size_t)l * 512;
        const float* f1w = fc1_w + (size_t)l * 512 * 2048;
        const float* f1b = fc1_b + (size_t)l * 2048;
        const float* f2w = fc2_w + (size_t)l * 2048 * 512;
        const float* f2b = fc2_b + (size_t)l * 512;

        ln_kernel<<<4096, 128>>>(px, n1_g + l * 512, n1_b + l * 512, pln, 1e-5f);
        sgemm_tf32_kernel<<<dim3(12, 32), 256>>>(pln, qw, qb, nullptr, pqkv, 4096, 1536, 512, 0);
        qkv_split_kernel<<<8192, 256>>>(pqkv, nq_g + l * 32, nq_b + l * 32,
                                        nk_g + l * 32, nk_b + l * 32, pq, pk, pv);
        flash_kernel<<<dim3(8, 64), 256, FLASH_SMEM>>>(pq, pk, pv, po);
        sgemm_tf32_kernel<<<dim3(4, 32), 256>>>(po, pw, pb, px, px2, 4096, 512, 512, 1);
        ln_kernel<<<4096, 128>>>(px2, n2_g + l * 512, n2_b + l * 512, pln, 1e-5f);
        sgemm_tf32_kernel<<<dim3(16, 32), 256>>>(pln, f1w, f1b, nullptr, pmlp, 4096, 2048, 512, 2);
        sgemm_tf32_kernel<<<dim3(4, 32), 256>>>(pmlp, f2w, f2b, px2, px, 4096, 512, 2048, 1);
    }

    ln_kernel<<<4096, 128>>>(px, nullptr, nullptr, pln, 1e-6f);
    sgemm_tf32_kernel<<<dim3(8, 32), 256>>>(pln, fin_w, fin_b, nullptr, pfin, 4096, 1024, 512, 0);
    unpatch_kernel<<<(4 * 64 * 128 * 128 + 255) / 256, 256>>>(pfin, pimg);
    conv1_kernel<<<(4 * 16 * 128 * 128 + 255) / 256, 256>>>(pimg, c1_w, c1_b, pc1);
    conv2_kernel<<<(4 * 3 * 128 * 128 + 255) / 256, 256>>>(pc1, c2_w, c2_b, out);
}

// round 7
// speedup vs baseline: 4.1611x; 1.2839x over previous
#include <cuda_runtime.h>
#include <cuda_fp16.h>
#include <math.h>
#include <stdint.h>

// ---------------- scratch (static device globals; no allocations) ----------
__device__ float g_x   [4096*512];
__device__ float g_x2  [4096*512];
__device__ float g_ln  [4096*512];
__device__ float g_qkv [4096*1536];
__device__ float g_mlp [4096*2048];
__device__ float g_q   [64*1024*32];
__device__ float g_k   [64*1024*32];
__device__ float g_v   [64*1024*32];
__device__ float g_o   [4096*512];
__device__ float g_fin [4096*1024];
__device__ float g_img [4*64*128*128];
__device__ float g_c1  [4*16*128*128];

// ---------------- helpers --------------------------------------------------
__device__ __forceinline__ uint32_t h2u(__half2 h) {
    return *reinterpret_cast<uint32_t*>(&h);
}

__device__ __forceinline__ void mma_f16(float* c, const uint32_t* a, const uint32_t* b) {
    asm volatile(
        "mma.sync.aligned.m16n8k16.row.col.f32.f16.f16.f32 "
        "{%0,%1,%2,%3}, {%4,%5,%6,%7}, {%8,%9}, {%0,%1,%2,%3};"
        : "+f"(c[0]), "+f"(c[1]), "+f"(c[2]), "+f"(c[3])
        : "r"(a[0]), "r"(a[1]), "r"(a[2]), "r"(a[3]), "r"(b[0]), "r"(b[1]));
}

// ---------------- pos-embed add (float math) -------------------------------
__global__ void add_pe_kernel(const float* __restrict__ x, float* __restrict__ out) {
    int idx = blockIdx.x * blockDim.x + threadIdx.x;
    if (idx >= 4 * 1024 * 512) return;
    int c = idx & 511;
    int p = (idx >> 9) & 1023;
    int i = p >> 5, j = p & 31;
    int pos = (c < 256) ? j : i;
    int cc = c & 255;
    int m = cc & 127;
    float om = __expf(-(float)m * 0.0719558141f);   // ln(10000)/128
    float a = (float)pos * om;
    float pe = (cc < 128) ? sinf(a) : cosf(a);
    out[idx] = x[idx] + pe;
}

// ---------------- layernorm over rows of 512 ------------------------------
__global__ void ln_kernel(const float* __restrict__ in, const float* __restrict__ g,
                          const float* __restrict__ b, float* __restrict__ out,
                          float eps) {
    int row = blockIdx.x;
    const float* x = in + (size_t)row * 512;
    int t = threadIdx.x;                       // 128 threads
    float v[4];
    float s = 0.f;
#pragma unroll
    for (int i = 0; i < 4; i++) { v[i] = x[t + i * 128]; s += v[i]; }
    __shared__ float red[128];
    red[t] = s; __syncthreads();
    for (int o = 64; o > 0; o >>= 1) { if (t < o) red[t] += red[t + o]; __syncthreads(); }
    float mu = red[0] * (1.f / 512.f);
    __syncthreads();
    float sq = 0.f;
#pragma unroll
    for (int i = 0; i < 4; i++) { float d = v[i] - mu; sq += d * d; }
    red[t] = sq; __syncthreads();
    for (int o = 64; o > 0; o >>= 1) { if (t < o) red[t] += red[t + o]; __syncthreads(); }
    float rstd = rsqrtf(red[0] * (1.f / 512.f) + eps);
#pragma unroll
    for (int i = 0; i < 4; i++) {
        int c = t + i * 128;
        float y = (v[i] - mu) * rstd;
        if (g) y = y * g[c] + b[c];
        out[(size_t)row * 512 + c] = y;
    }
}

// ---------------- fp16 tensor-core SGEMM ----------------------------------
// C = A(MxK)*B(KxN)+bias [mode1:+res, mode2:GELU]. 256 thr, tile 128x128, Kblk 32.
// warps 2(M)x4(N), warp tile 64x32 = 4x4 m16n8k16 tiles (2 k-steps / Kblk).
// Smem As: [128 rows][20 half2 words] (t=20, conflict-free g/tig loads)
//      Bs: [128 n]   [20 half2 words] k-paired (word p = keys 2p,2p+1)
__global__ void sgemm_f16_kernel(const float* __restrict__ A, const float* __restrict__ B,
                                 const float* __restrict__ bias, const float* __restrict__ res,
                                 float* __restrict__ C, int M, int N, int K, int mode) {
    __shared__ uint32_t As[128 * 20];
    __shared__ uint32_t Bs[128 * 20];
    int tid = threadIdx.x;
    int w = tid >> 5, lane = tid & 31;
    int g = lane >> 2, tig = lane & 3;
    int warp_m = w & 1, warp_n = w >> 1;
    int bm = blockIdx.y * 128, bn = blockIdx.x * 128;

    float acc[4][4][4] = {};
    float4 pa[4];
    float2 pb[8];

#pragma unroll
    for (int i = 0; i < 4; i++) {
        int idx = i * 256 + tid;
        int row = idx >> 3, kv = idx & 7;
        pa[i] = *(const float4*)&A[(size_t)(bm + row) * K + kv * 4];
    }
#pragma unroll
    for (int i = 0; i < 8; i++) {
        int idx = i * 256 + tid;
        int p = idx >> 7, n = idx & 127;
        pb[i].x = B[(size_t)(2 * p) * N + bn + n];
        pb[i].y = B[(size_t)(2 * p + 1) * N + bn + n];
    }

    for (int k0 = 0; k0 < K; k0 += 32) {
#pragma unroll
        for (int i = 0; i < 4; i++) {
            int idx = i * 256 + tid;
            int row = idx >> 3, kv = idx & 7;
            As[row * 20 + 2 * kv]     = h2u(__floats2half2_rn(pa[i].x, pa[i].y));
            As[row * 20 + 2 * kv + 1] = h2u(__floats2half2_rn(pa[i].z, pa[i].w));
        }
#pragma unroll
        for (int i = 0; i < 8; i++) {
            int idx = i * 256 + tid;
            int p = idx >> 7, n = idx & 127;
            Bs[n * 20 + p] = h2u(__floats2half2_rn(pb[i].x, pb[i].y));
        }
        __syncthreads();
        if (k0 + 32 < K) {
#pragma unroll
            for (int i = 0; i < 4; i++) {
                int idx = i * 256 + tid;
                int row = idx >> 3, kv = idx & 7;
                pa[i] = *(const float4*)&A[(size_t)(bm + row) * K + k0 + 32 + kv * 4];
            }
#pragma unroll
            for (int i = 0; i < 8; i++) {
                int idx = i * 256 + tid;
                int p = idx >> 7, n = idx & 127;
                pb[i].x = B[(size_t)(k0 + 32 + 2 * p) * N + bn + n];
                pb[i].y = B[(size_t)(k0 + 32 + 2 * p + 1) * N + bn + n];
            }
        }
#pragma unroll
        for (int ks = 0; ks < 2; ks++) {
            int kw = ks * 8;
            uint32_t a[4][4], b[4][2];
#pragma unroll
            for (int mt = 0; mt < 4; mt++) {
                int mr = warp_m * 64 + mt * 16;
                a[mt][0] = As[(mr + g) * 20 + kw + tig];
                a[mt][1] = As[(mr + 8 + g) * 20 + kw + tig];
                a[mt][2] = As[(mr + g) * 20 + kw + 4 + tig];
                a[mt][3] = As[(mr + 8 + g) * 20 + kw + 4 + tig];
            }
#pragma unroll
            for (int nt = 0; nt < 4; nt++) {
                int nc = warp_n * 32 + nt * 8;
                b[nt][0] = Bs[(nc + g) * 20 + kw + tig];
                b[nt][1] = Bs[(nc + g) * 20 + kw + 4 + tig];
            }
#pragma unroll
            for (int mt = 0; mt < 4; mt++)
#pragma unroll
                for (int nt = 0; nt < 4; nt++)
                    mma_f16(acc[mt][nt], a[mt], b[nt]);
        }
        __syncthreads();
    }

#pragma unroll
    for (int mt = 0; mt < 4; mt++) {
#pragma unroll
        for (int nt = 0; nt < 4; nt++) {
            int row0 = bm + warp_m * 64 + mt * 16 + g;
            int col0 = bn + warp_n * 32 + nt * 8 + 2 * tig;
#pragma unroll
            for (int i = 0; i < 4; i++) {
                int row = row0 + (i >> 1) * 8;
                int col = col0 + (i & 1);
                float v = acc[mt][nt][i] + bias[col];
                if (mode == 1) v += res[(size_t)row * N + col];
                else if (mode == 2) v = 0.5f * v * (1.f + erff(v * 0.70710678118654752f));
                C[(size_t)row * N + col] = v;
            }
        }
    }
}

// ---------------- qkv split + q/k head-LN (HEAD_D=32); q pre-scaled -------
__global__ void qkv_split_kernel(const float* __restrict__ qkv,
                                 const float* __restrict__ nqg, const float* __restrict__ nqb,
                                 const float* __restrict__ nkg, const float* __restrict__ nkb,
                                 float* __restrict__ q, float* __restrict__ k,
                                 float* __restrict__ v) {
    int warp = (blockIdx.x * blockDim.x + threadIdx.x) >> 5;
    int lane = threadIdx.x & 31;
    if (warp >= 4096 * 16) return;
    int t = warp >> 4;
    int h = warp & 15;
    int b = t >> 10, n = t & 1023;
    const float* base = qkv + (size_t)t * 1536 + h * 32;
    float qv = base[lane];
    float kv = base[512 + lane];
    float vv = base[1024 + lane];

    float sq = qv, sk = kv;
#pragma unroll
    for (int o = 16; o > 0; o >>= 1) {
        sq += __shfl_xor_sync(0xffffffffu, sq, o);
        sk += __shfl_xor_sync(0xffffffffu, sk, o);
    }
    float mq = sq * (1.f / 32.f), mk = sk * (1.f / 32.f);
    float dq = qv - mq, dk = kv - mk;
    float vq = dq * dq, vk = dk * dk;
#pragma unroll
    for (int o = 16; o > 0; o >>= 1) {
        vq += __shfl_xor_sync(0xffffffffu, vq, o);
        vk += __shfl_xor_sync(0xffffffffu, vk, o);
    }
    float rq = rsqrtf(vq * (1.f / 32.f) + 1e-5f);
    float rk = rsqrtf(vk * (1.f / 32.f) + 1e-5f);
    const float sc = 0.17677669529663689f;   // 1/sqrt(32), folded into q
    size_t ob = ((size_t)(b * 16 + h) * 1024 + n) * 32;
    q[ob + lane] = (dq * rq * nqg[lane] + nqb[lane]) * sc;
    k[ob + lane] = dk * rk * nkg[lane] + nkb[lane];
    v[ob + lane] = vv;
}

// ---------------- flash attention (fp16 MMA) -------------------------------
// grid (8 qblocks, 64 bh), 256 thr. Warp owns 16 q rows. 64-key tiles.
// Qs/Ks: [rows][20 words]; Vs: [d 32][36 words] key-paired; Ps per-warp [16][36].
__global__ void flash_kernel(const float* __restrict__ q, const float* __restrict__ k,
                             const float* __restrict__ v, float* __restrict__ o) {
    __shared__ uint32_t Qs[128 * 20];
    __shared__ uint32_t Ks[64 * 20];
    __shared__ uint32_t Vs[32 * 36];
    __shared__ uint32_t Ps[8 * 16 * 36];

    int bh = blockIdx.y;
    int bm = blockIdx.x * 128;
    int b = bh >> 4, h = bh & 15;
    int tid = threadIdx.x;
    int w = tid >> 5, lane = tid & 31;
    int g = lane >> 2, tig = lane & 3;

    const float* qb = q + ((size_t)bh * 1024 + bm) * 32;
    const float* kb = k + (size_t)bh * 1024 * 32;
    const float* vb = v + (size_t)bh * 1024 * 32;

    // load Q tile (128x32) -> smem fp16
#pragma unroll
    for (int i = 0; i < 4; i++) {
        int idx = i * 256 + tid;
        int r = idx >> 3, dv = idx & 7;
        float4 t = *(const float4*)&qb[r * 32 + dv * 4];
        Qs[r * 20 + 2 * dv]     = h2u(__floats2half2_rn(t.x, t.y));
        Qs[r * 20 + 2 * dv + 1] = h2u(__floats2half2_rn(t.z, t.w));
    }
    __syncthreads();

    // persistent Q fragments: 2 k-steps (d=32)
    uint32_t qa[2][4];
    int wr = w * 16;
#pragma unroll
    for (int ks = 0; ks < 2; ks++) {
        int kw = ks * 8;
        qa[ks][0] = Qs[(wr + g) * 20 + kw + tig];
        qa[ks][1] = Qs[(wr + 8 + g) * 20 + kw + tig];
        qa[ks][2] = Qs[(wr + g) * 20 + kw + 4 + tig];
        qa[ks][3] = Qs[(wr + 8 + g) * 20 + kw + 4 + tig];
    }

    float oacc[4][4] = {};
    float m0 = -1e30f, m1 = -1e30f, l0 = 0.f, l1 = 0.f;
    uint32_t* Pw = Ps + w * 16 * 36;

    for (int j = 0; j < 16; j++) {
        __syncthreads();   // protect Ks/Vs vs previous iteration's reads
        // K tile 64x32 fp16
#pragma unroll
        for (int i = 0; i < 2; i++) {
            int idx = i * 256 + tid;
            int r = idx >> 3, dv = idx & 7;
            float4 t = *(const float4*)&kb[(size_t)(j * 64 + r) * 32 + dv * 4];
            Ks[r * 20 + 2 * dv]     = h2u(__floats2half2_rn(t.x, t.y));
            Ks[r * 20 + 2 * dv + 1] = h2u(__floats2half2_rn(t.z, t.w));
        }
        // V tile 64x32 -> transposed key-paired: Vs[d][pair] = (v[2p][d], v[2p+1][d])
#pragma unroll
        for (int i = 0; i < 4; i++) {
            int idx = i * 256 + tid;
            int p = idx >> 5, d = idx & 31;
            float v0 = vb[(size_t)(j * 64 + 2 * p) * 32 + d];
            float v1 = vb[(size_t)(j * 64 + 2 * p + 1) * 32 + d];
            Vs[d * 36 + p] = h2u(__floats2half2_rn(v0, v1));
        }
        __syncthreads();

        // S = Q K^T : warp computes 16x64
        float s[8][4] = {};
#pragma unroll
        for (int ks = 0; ks < 2; ks++) {
            int kw = ks * 8;
            uint32_t bf[8][2];
#pragma unroll
            for (int nt = 0; nt < 8; nt++) {
                int nc = nt * 8;
                bf[nt][0] = Ks[(nc + g) * 20 + kw + tig];
                bf[nt][1] = Ks[(nc + g) * 20 + kw + 4 + tig];
            }
#pragma unroll
            for (int nt = 0; nt < 8; nt++)
                mma_f16(s[nt], qa[ks], bf[nt]);
        }

        // online softmax (rows g and g+8)
        float rm0 = -1e30f, rm1 = -1e30f;
#pragma unroll
        for (int nt = 0; nt < 8; nt++) {
            rm0 = fmaxf(rm0, fmaxf(s[nt][0], s[nt][1]));
            rm1 = fmaxf(rm1, fmaxf(s[nt][2], s[nt][3]));
        }
        rm0 = fmaxf(rm0, __shfl_xor_sync(0xffffffffu, rm0, 1));
        rm0 = fmaxf(rm0, __shfl_xor_sync(0xffffffffu, rm0, 2));
        rm1 = fmaxf(rm1, __shfl_xor_sync(0xffffffffu, rm1, 1));
        rm1 = fmaxf(rm1, __shfl_xor_sync(0xffffffffu, rm1, 2));
        float nm0 = fmaxf(m0, rm0), nm1 = fmaxf(m1, rm1);
        float al0 = __expf(m0 - nm0), al1 = __expf(m1 - nm1);
        float rs0 = 0.f, rs1 = 0.f;
#pragma unroll
        for (int nt = 0; nt < 8; nt++) {
            s[nt][0] = __expf(s[nt][0] - nm0);
            s[nt][1] = __expf(s[nt][1] - nm0);
            s[nt][2] = __expf(s[nt][2] - nm1);
            s[nt][3] = __expf(s[nt][3] - nm1);
            rs0 += s[nt][0] + s[nt][1];
            rs1 += s[nt][2] + s[nt][3];
        }
        rs0 += __shfl_xor_sync(0xffffffffu, rs0, 1);
        rs0 += __shfl_xor_sync(0xffffffffu, rs0, 2);
        rs1 += __shfl_xor_sync(0xffffffffu, rs1, 1);
        rs1 += __shfl_xor_sync(0xffffffffu, rs1, 2);
        l0 = l0 * al0 + rs0;
        l1 = l1 * al1 + rs1;
        m0 = nm0; m1 = nm1;
#pragma unroll
        for (int nt = 0; nt < 4; nt++) {
            oacc[nt][0] *= al0; oacc[nt][1] *= al0;
            oacc[nt][2] *= al1; oacc[nt][3] *= al1;
        }

        // store P fp16 to per-warp smem (row stride 36 words)
#pragma unroll
        for (int nt = 0; nt < 8; nt++) {
            Pw[g * 36 + nt * 4 + tig]       = h2u(__floats2half2_rn(s[nt][0], s[nt][1]));
            Pw[(8 + g) * 36 + nt * 4 + tig] = h2u(__floats2half2_rn(s[nt][2], s[nt][3]));
        }
        __syncwarp();

        // O += P @ V : 4 k-steps (64 keys), 4 n-tiles (32 d)
#pragma unroll
        for (int ks2 = 0; ks2 < 4; ks2++) {
            int kw = ks2 * 8;
            uint32_t a[4];
            a[0] = Pw[g * 36 + kw + tig];
            a[1] = Pw[(8 + g) * 36 + kw + tig];
            a[2] = Pw[g * 36 + kw + 4 + tig];
            a[3] = Pw[(8 + g) * 36 + kw + 4 + tig];
            uint32_t bf[4][2];
#pragma unroll
            for (int nt = 0; nt < 4; nt++) {
                int nc = nt * 8;
                bf[nt][0] = Vs[(nc + g) * 36 + kw + tig];
                bf[nt][1] = Vs[(nc + g) * 36 + kw + 4 + tig];
            }
#pragma unroll
            for (int nt = 0; nt < 4; nt++)
                mma_f16(oacc[nt], a, bf[nt]);
        }
        __syncwarp();
    }

    float il0 = 1.f / l0, il1 = 1.f / l1;
    int n0 = bm + w * 16 + g;
#pragma unroll
    for (int nt = 0; nt < 4; nt++) {
        int col = h * 32 + nt * 8 + 2 * tig;
        o[((size_t)(b * 1024 + n0)) * 512 + col]     = oacc[nt][0] * il0;
        o[((size_t)(b * 1024 + n0)) * 512 + col + 1] = oacc[nt][1] * il0;
        o[((size_t)(b * 1024 + n0 + 8)) * 512 + col]     = oacc[nt][2] * il1;
        o[((size_t)(b * 1024 + n0 + 8)) * 512 + col + 1] = oacc[nt][3] * il1;
    }
}

// ---------------- unpatchify ----------------------------------------------
__global__ void unpatch_kernel(const float* __restrict__ fin, float* __restrict__ img) {
    int idx = blockIdx.x * blockDim.x + threadIdx.x;
    if (idx >= 4 * 64 * 128 * 128) return;
    int W = idx & 127;
    int H = (idx >> 7) & 127;
    int c = (idx >> 14) & 63;
    int b = idx >> 20;
    int hh = H >> 2, p = H & 3, ww = W >> 2, qq = W & 3;
    img[idx] = fin[((size_t)(b * 1024 + hh * 32 + ww)) * 1024 + c * 16 + p * 4 + qq];
}

// ---------------- conv1: smem-tiled 3x3, 64->16 ch, ReLU -------------------
// grid (64 tiles, 4 batch), 256 thr = 16x16 outputs, all 16 oc per thread.
__global__ void conv1_kernel(const float* __restrict__ img, const float* __restrict__ w,
                             const float* __restrict__ bias, float* __restrict__ out) {
    __shared__ float patch[18 * 18];
    __shared__ float wsm[16 * 9];
    int b = blockIdx.y;
    int tile = blockIdx.x;
    int Y0 = (tile >> 3) * 16, X0 = (tile & 7) * 16;
    int tid = threadIdx.x;
    int ty = tid >> 4, tx = tid & 15;
    float acc[16];
#pragma unroll
    for (int oc = 0; oc < 16; oc++) acc[oc] = bias[oc];

    for (int ic = 0; ic < 64; ic++) {
        __syncthreads();
        const float* ip = img + ((size_t)(b * 64 + ic)) * 16384;
        for (int idx = tid; idx < 324; idx += 256) {
            int py = idx / 18, px = idx % 18;
            int gy = Y0 + py - 1, gx = X0 + px - 1;
            patch[idx] = (gy >= 0 && gy < 128 && gx >= 0 && gx < 128) ? ip[gy * 128 + gx] : 0.f;
        }
        if (tid < 144) wsm[tid] = w[(size_t)((tid / 9) * 64 + ic) * 9 + (tid % 9)];
        __syncthreads();
        float p[9];
#pragma unroll
        for (int ky = 0; ky < 3; ky++)
#pragma unroll
            for (int kx = 0; kx < 3; kx++)
                p[ky * 3 + kx] = patch[(ty + ky) * 18 + tx + kx];
#pragma unroll
        for (int oc = 0; oc < 16; oc++) {
            float a = 0.f;
#pragma unroll
            for (int t = 0; t < 9; t++) a += p[t] * wsm[oc * 9 + t];
            acc[oc] += a;
        }
    }
#pragma unroll
    for (int oc = 0; oc < 16; oc++)
        out[((size_t)(b * 16 + oc)) * 16384 + (Y0 + ty) * 128 + X0 + tx] = fmaxf(acc[oc], 0.f);
}

// ---------------- conv2: 3x3, 16->3 ch -------------------------------------
__global__ void conv2_kernel(const float* __restrict__ img, const float* __restrict__ w,
                             const float* __restrict__ bias, float* __restrict__ out) {
    int idx = blockIdx.x * blockDim.x + threadIdx.x;
    if (idx >= 4 * 3 * 128 * 128) return;
    int x = idx & 127, y = (idx >> 7) & 127;
    int oc = (idx >> 14) % 3, b = idx / (3 * 16384);
    float acc = bias[oc];
    for (int ic = 0; ic < 16; ic++) {
        const float* ip = img + ((size_t)(b * 16 + ic)) * 16384;
        const float* wp = w + (size_t)(oc * 16 + ic) * 9;
#pragma unroll
        for (int ky = 0; ky < 3; ky++) {
            int yy = y + ky - 1;
            if (yy < 0 || yy > 127) continue;
#pragma unroll
            for (int kx = 0; kx < 3; kx++) {
                int xx = x + kx - 1;
                if (xx < 0 || xx > 127) continue;
                acc += ip[yy * 128 + xx] * wp[ky * 3 + kx];
            }
        }
    }
    out[idx] = acc;
}

// ---------------- driver ---------------------------------------------------
extern "C" void kernel_launch(void* const* d_in, const int* in_sizes, int n_in,
                              void* d_out, int out_size) {
    const float* x_in  = (const float*)d_in[0];
    const float* qkv_w = (const float*)d_in[1];
    const float* qkv_b = (const float*)d_in[2];
    const float* proj_w= (const float*)d_in[3];
    const float* proj_b= (const float*)d_in[4];
    const float* nq_g  = (const float*)d_in[5];
    const float* nq_b  = (const float*)d_in[6];
    const float* nk_g  = (const float*)d_in[7];
    const float* nk_b  = (const float*)d_in[8];
    const float* n1_g  = (const float*)d_in[9];
    const float* n1_b  = (const float*)d_in[10];
    const float* n2_g  = (const float*)d_in[11];
    const float* n2_b  = (const float*)d_in[12];
    const float* fc1_w = (const float*)d_in[13];
    const float* fc1_b = (const float*)d_in[14];
    const float* fc2_w = (const float*)d_in[15];
    const float* fc2_b = (const float*)d_in[16];
    const float* fin_w = (const float*)d_in[17];
    const float* fin_b = (const float*)d_in[18];
    const float* c1_w  = (const float*)d_in[19];
    const float* c1_b  = (const float*)d_in[20];
    const float* c2_w  = (const float*)d_in[21];
    const float* c2_b  = (const float*)d_in[22];
    float* out = (float*)d_out;

    float *px, *px2, *pln, *pqkv, *pmlp, *pq, *pk, *pv, *po, *pfin, *pimg, *pc1;
    cudaGetSymbolAddress((void**)&px,   g_x);
    cudaGetSymbolAddress((void**)&px2,  g_x2);
    cudaGetSymbolAddress((void**)&pln,  g_ln);
    cudaGetSymbolAddress((void**)&pqkv, g_qkv);
    cudaGetSymbolAddress((void**)&pmlp, g_mlp);
    cudaGetSymbolAddress((void**)&pq,   g_q);
    cudaGetSymbolAddress((void**)&pk,   g_k);
    cudaGetSymbolAddress((void**)&pv,   g_v);
    cudaGetSymbolAddress((void**)&po,   g_o);
    cudaGetSymbolAddress((void**)&pfin, g_fin);
    cudaGetSymbolAddress((void**)&pimg, g_img);
    cudaGetSymbolAddress((void**)&pc1,  g_c1);

    add_pe_kernel<<<(4 * 1024 * 512 + 255) / 256, 256>>>(x_in, px);

    for (int l = 0; l < 8; l++) {
        const float* qw = qkv_w + (size_t)l * 512 * 1536;
        const float* qb = qkv_b + (size_t)l * 1536;
        const float* pw = proj_w + (size_t)l * 512 * 512;
        const float* pb = proj_b + (size_t)l * 512;
        const float* f1w = fc1_w + (size_t)l * 512 * 2048;
        const float* f1b = fc1_b + (size_t)l * 2048;
        const float* f2w = fc2_w + (size_t)l * 2048 * 512;
        const float* f2b = fc2_b + (size_t)l * 512;

        ln_kernel<<<4096, 128>>>(px, n1_g + l * 512, n1_b + l * 512, pln, 1e-5f);
        sgemm_f16_kernel<<<dim3(12, 32), 256>>>(pln, qw, qb, nullptr, pqkv, 4096, 1536, 512, 0);
        qkv_split_kernel<<<8192, 256>>>(pqkv, nq_g + l * 32, nq_b + l * 32,
                                        nk_g + l * 32, nk_b + l * 32, pq, pk, pv);
        flash_kernel<<<dim3(8, 64), 256>>>(pq, pk, pv, po);
        sgemm_f16_kernel<<<dim3(4, 32), 256>>>(po, pw, pb, px, px2, 4096, 512, 512, 1);
        ln_kernel<<<4096, 128>>>(px2, n2_g + l * 512, n2_b + l * 512, pln, 1e-5f);
        sgemm_f16_kernel<<<dim3(16, 32), 256>>>(pln, f1w, f1b, nullptr, pmlp, 4096, 2048, 512, 2);
        sgemm_f16_kernel<<<dim3(4, 32), 256>>>(pmlp, f2w, f2b, px2, px, 4096, 512, 2048, 1);
    }

    ln_kernel<<<4096, 128>>>(px, nullptr, nullptr, pln, 1e-6f);
    sgemm_f16_kernel<<<dim3(8, 32), 256>>>(pln, fin_w, fin_b, nullptr, pfin, 4096, 1024, 512, 0);
    unpatch_kernel<<<(4 * 64 * 128 * 128 + 255) / 256, 256>>>(pfin, pimg);
    conv1_kernel<<<dim3(64, 4), 256>>>(pimg, c1_w, c1_b, pc1);
    conv2_kernel<<<(4 * 3 * 128 * 128 + 255) / 256, 256>>>(pc1, c2_w, c2_b, out);
}

// round 8
// speedup vs baseline: 4.4607x; 1.0720x over previous
#include <cuda_runtime.h>
#include <cuda_fp16.h>
#include <math.h>
#include <stdint.h>

// ---------------- scratch (static device globals; no allocations) ----------
__device__ float g_x   [4096*512];
__device__ float g_x2  [4096*512];
__device__ float g_ln  [4096*512];
__device__ float g_mlp [4096*2048];
__device__ float g_q   [64*1024*32];
__device__ float g_k   [64*1024*32];
__device__ float g_v   [64*1024*32];
__device__ float g_o   [4096*512];
__device__ float g_fin [4096*1024];
__device__ float g_img [4*64*128*128];
__device__ float g_c1  [4*16*128*128];

// ---------------- helpers --------------------------------------------------
__device__ __forceinline__ uint32_t h2u(__half2 h) {
    return *reinterpret_cast<uint32_t*>(&h);
}

__device__ __forceinline__ void mma_f16(float* c, const uint32_t* a, const uint32_t* b) {
    asm volatile(
        "mma.sync.aligned.m16n8k16.row.col.f32.f16.f16.f32 "
        "{%0,%1,%2,%3}, {%4,%5,%6,%7}, {%8,%9}, {%0,%1,%2,%3};"
        : "+f"(c[0]), "+f"(c[1]), "+f"(c[2]), "+f"(c[3])
        : "r"(a[0]), "r"(a[1]), "r"(a[2]), "r"(a[3]), "r"(b[0]), "r"(b[1]));
}

// ---------------- pos-embed add (float math) -------------------------------
__global__ void add_pe_kernel(const float* __restrict__ x, float* __restrict__ out) {
    int idx = blockIdx.x * blockDim.x + threadIdx.x;
    if (idx >= 4 * 1024 * 512) return;
    int c = idx & 511;
    int p = (idx >> 9) & 1023;
    int i = p >> 5, j = p & 31;
    int pos = (c < 256) ? j : i;
    int cc = c & 255;
    int m = cc & 127;
    float om = __expf(-(float)m * 0.0719558141f);   // ln(10000)/128
    float a = (float)pos * om;
    float pe = (cc < 128) ? sinf(a) : cosf(a);
    out[idx] = x[idx] + pe;
}

// ---------------- layernorm: one warp per 512-row, float4 + shfl ----------
__global__ void ln_kernel(const float* __restrict__ in, const float* __restrict__ g,
                          const float* __restrict__ b, float* __restrict__ out,
                          float eps) {
    int row = (blockIdx.x * blockDim.x + threadIdx.x) >> 5;
    int lane = threadIdx.x & 31;
    if (row >= 4096) return;
    const float4* x = (const float4*)(in + (size_t)row * 512);
    float4 v[4];
    float s = 0.f;
#pragma unroll
    for (int i = 0; i < 4; i++) {
        v[i] = x[lane + i * 32];
        s += v[i].x + v[i].y + v[i].z + v[i].w;
    }
#pragma unroll
    for (int o = 16; o > 0; o >>= 1) s += __shfl_xor_sync(0xffffffffu, s, o);
    float mu = s * (1.f / 512.f);
    float sq = 0.f;
#pragma unroll
    for (int i = 0; i < 4; i++) {
        float dx = v[i].x - mu, dy = v[i].y - mu, dz = v[i].z - mu, dw = v[i].w - mu;
        sq += dx * dx + dy * dy + dz * dz + dw * dw;
    }
#pragma unroll
    for (int o = 16; o > 0; o >>= 1) sq += __shfl_xor_sync(0xffffffffu, sq, o);
    float rstd = rsqrtf(sq * (1.f / 512.f) + eps);
    float4* op = (float4*)(out + (size_t)row * 512);
#pragma unroll
    for (int i = 0; i < 4; i++) {
        float4 y;
        y.x = (v[i].x - mu) * rstd; y.y = (v[i].y - mu) * rstd;
        y.z = (v[i].z - mu) * rstd; y.w = (v[i].w - mu) * rstd;
        if (g) {
            float4 gg = ((const float4*)g)[lane + i * 32];
            float4 bb = ((const float4*)b)[lane + i * 32];
            y.x = y.x * gg.x + bb.x; y.y = y.y * gg.y + bb.y;
            y.z = y.z * gg.z + bb.z; y.w = y.w * gg.w + bb.w;
        }
        op[lane + i * 32] = y;
    }
}

// ---------------- fp16 tensor-core SGEMM (generic) -------------------------
// C = A(MxK)*B(KxN)+bias [mode1:+res, mode2:GELU]. 256 thr, tile 128x128, Kblk 32.
__global__ void sgemm_f16_kernel(const float* __restrict__ A, const float* __restrict__ B,
                                 const float* __restrict__ bias, const float* __restrict__ res,
                                 float* __restrict__ C, int M, int N, int K, int mode) {
    __shared__ uint32_t As[128 * 20];
    __shared__ uint32_t Bs[128 * 20];
    int tid = threadIdx.x;
    int w = tid >> 5, lane = tid & 31;
    int g = lane >> 2, tig = lane & 3;
    int warp_m = w & 1, warp_n = w >> 1;
    int bm = blockIdx.y * 128, bn = blockIdx.x * 128;

    float acc[4][4][4] = {};
    float4 pa[4];
    float2 pb[8];

#pragma unroll
    for (int i = 0; i < 4; i++) {
        int idx = i * 256 + tid;
        int row = idx >> 3, kv = idx & 7;
        pa[i] = *(const float4*)&A[(size_t)(bm + row) * K + kv * 4];
    }
#pragma unroll
    for (int i = 0; i < 8; i++) {
        int idx = i * 256 + tid;
        int p = idx >> 7, n = idx & 127;
        pb[i].x = B[(size_t)(2 * p) * N + bn + n];
        pb[i].y = B[(size_t)(2 * p + 1) * N + bn + n];
    }

    for (int k0 = 0; k0 < K; k0 += 32) {
#pragma unroll
        for (int i = 0; i < 4; i++) {
            int idx = i * 256 + tid;
            int row = idx >> 3, kv = idx & 7;
            As[row * 20 + 2 * kv]     = h2u(__floats2half2_rn(pa[i].x, pa[i].y));
            As[row * 20 + 2 * kv + 1] = h2u(__floats2half2_rn(pa[i].z, pa[i].w));
        }
#pragma unroll
        for (int i = 0; i < 8; i++) {
            int idx = i * 256 + tid;
            int p = idx >> 7, n = idx & 127;
            Bs[n * 20 + p] = h2u(__floats2half2_rn(pb[i].x, pb[i].y));
        }
        __syncthreads();
        if (k0 + 32 < K) {
#pragma unroll
            for (int i = 0; i < 4; i++) {
                int idx = i * 256 + tid;
                int row = idx >> 3, kv = idx & 7;
                pa[i] = *(const float4*)&A[(size_t)(bm + row) * K + k0 + 32 + kv * 4];
            }
#pragma unroll
            for (int i = 0; i < 8; i++) {
                int idx = i * 256 + tid;
                int p = idx >> 7, n = idx & 127;
                pb[i].x = B[(size_t)(k0 + 32 + 2 * p) * N + bn + n];
                pb[i].y = B[(size_t)(k0 + 32 + 2 * p + 1) * N + bn + n];
            }
        }
#pragma unroll
        for (int ks = 0; ks < 2; ks++) {
            int kw = ks * 8;
            uint32_t a[4][4], b[4][2];
#pragma unroll
            for (int mt = 0; mt < 4; mt++) {
                int mr = warp_m * 64 + mt * 16;
                a[mt][0] = As[(mr + g) * 20 + kw + tig];
                a[mt][1] = As[(mr + 8 + g) * 20 + kw + tig];
                a[mt][2] = As[(mr + g) * 20 + kw + 4 + tig];
                a[mt][3] = As[(mr + 8 + g) * 20 + kw + 4 + tig];
            }
#pragma unroll
            for (int nt = 0; nt < 4; nt++) {
                int nc = warp_n * 32 + nt * 8;
                b[nt][0] = Bs[(nc + g) * 20 + kw + tig];
                b[nt][1] = Bs[(nc + g) * 20 + kw + 4 + tig];
            }
#pragma unroll
            for (int mt = 0; mt < 4; mt++)
#pragma unroll
                for (int nt = 0; nt < 4; nt++)
                    mma_f16(acc[mt][nt], a[mt], b[nt]);
        }
        __syncthreads();
    }

#pragma unroll
    for (int mt = 0; mt < 4; mt++) {
#pragma unroll
        for (int nt = 0; nt < 4; nt++) {
            int row0 = bm + warp_m * 64 + mt * 16 + g;
            int col0 = bn + warp_n * 32 + nt * 8 + 2 * tig;
#pragma unroll
            for (int i = 0; i < 4; i++) {
                int row = row0 + (i >> 1) * 8;
                int col = col0 + (i & 1);
                float v = acc[mt][nt][i] + bias[col];
                if (mode == 1) v += res[(size_t)row * N + col];
                else if (mode == 2) v = 0.5f * v * (1.f + erff(v * 0.70710678118654752f));
                C[(size_t)row * N + col] = v;
            }
        }
    }
}

// ---------------- QKV GEMM with fused head-split + q/k head-LN ------------
// Same mainloop as generic (N=1536, K=512). Epilogue: warp's 32-col span is one
// head's channels; head-LN via 2 shfl_xor over the tig group; writes g_q/g_k/g_v.
__global__ void sgemm_qkv_kernel(const float* __restrict__ A, const float* __restrict__ B,
                                 const float* __restrict__ bias,
                                 const float* __restrict__ nqg, const float* __restrict__ nqb,
                                 const float* __restrict__ nkg, const float* __restrict__ nkb,
                                 float* __restrict__ q, float* __restrict__ k,
                                 float* __restrict__ v) {
    const int N = 1536, K = 512;
    __shared__ uint32_t As[128 * 20];
    __shared__ uint32_t Bs[128 * 20];
    int tid = threadIdx.x;
    int w = tid >> 5, lane = tid & 31;
    int g = lane >> 2, tig = lane & 3;
    int warp_m = w & 1, warp_n = w >> 1;
    int bm = blockIdx.y * 128, bn = blockIdx.x * 128;

    float acc[4][4][4] = {};
    float4 pa[4];
    float2 pb[8];

#pragma unroll
    for (int i = 0; i < 4; i++) {
        int idx = i * 256 + tid;
        int row = idx >> 3, kv = idx & 7;
        pa[i] = *(const float4*)&A[(size_t)(bm + row) * K + kv * 4];
    }
#pragma unroll
    for (int i = 0; i < 8; i++) {
        int idx = i * 256 + tid;
        int p = idx >> 7, n = idx & 127;
        pb[i].x = B[(size_t)(2 * p) * N + bn + n];
        pb[i].y = B[(size_t)(2 * p + 1) * N + bn + n];
    }

    for (int k0 = 0; k0 < K; k0 += 32) {
#pragma unroll
        for (int i = 0; i < 4; i++) {
            int idx = i * 256 + tid;
            int row = idx >> 3, kv = idx & 7;
            As[row * 20 + 2 * kv]     = h2u(__floats2half2_rn(pa[i].x, pa[i].y));
            As[row * 20 + 2 * kv + 1] = h2u(__floats2half2_rn(pa[i].z, pa[i].w));
        }
#pragma unroll
        for (int i = 0; i < 8; i++) {
            int idx = i * 256 + tid;
            int p = idx >> 7, n = idx & 127;
            Bs[n * 20 + p] = h2u(__floats2half2_rn(pb[i].x, pb[i].y));
        }
        __syncthreads();
        if (k0 + 32 < K) {
#pragma unroll
            for (int i = 0; i < 4; i++) {
                int idx = i * 256 + tid;
                int row = idx >> 3, kv = idx & 7;
                pa[i] = *(const float4*)&A[(size_t)(bm + row) * K + k0 + 32 + kv * 4];
            }
#pragma unroll
            for (int i = 0; i < 8; i++) {
                int idx = i * 256 + tid;
                int p = idx >> 7, n = idx & 127;
                pb[i].x = B[(size_t)(k0 + 32 + 2 * p) * N + bn + n];
                pb[i].y = B[(size_t)(k0 + 32 + 2 * p + 1) * N + bn + n];
            }
        }
#pragma unroll
        for (int ks = 0; ks < 2; ks++) {
            int kw = ks * 8;
            uint32_t a[4][4], b[4][2];
#pragma unroll
            for (int mt = 0; mt < 4; mt++) {
                int mr = warp_m * 64 + mt * 16;
                a[mt][0] = As[(mr + g) * 20 + kw + tig];
                a[mt][1] = As[(mr + 8 + g) * 20 + kw + tig];
                a[mt][2] = As[(mr + g) * 20 + kw + 4 + tig];
                a[mt][3] = As[(mr + 8 + g) * 20 + kw + 4 + tig];
            }
#pragma unroll
            for (int nt = 0; nt < 4; nt++) {
                int nc = warp_n * 32 + nt * 8;
                b[nt][0] = Bs[(nc + g) * 20 + kw + tig];
                b[nt][1] = Bs[(nc + g) * 20 + kw + 4 + tig];
            }
#pragma unroll
            for (int mt = 0; mt < 4; mt++)
#pragma unroll
                for (int nt = 0; nt < 4; nt++)
                    mma_f16(acc[mt][nt], a[mt], b[nt]);
        }
        __syncthreads();
    }

    // fused epilogue
    int colbase = bn + warp_n * 32;       // 32-aligned -> one head
    int sec = colbase >> 9;               // 0=q, 1=k, 2=v
    int h = (colbase & 511) >> 5;
    const float sc = 0.17677669529663689f;
    const float* gam = (sec == 0) ? nqg : nkg;
    const float* bet = (sec == 0) ? nqb : nkb;
    float* dst = (sec == 0) ? q : ((sec == 1) ? k : v);

#pragma unroll
    for (int mt = 0; mt < 4; mt++) {
#pragma unroll
        for (int rh = 0; rh < 2; rh++) {
            int row = bm + warp_m * 64 + mt * 16 + g + rh * 8;
            int bb = row >> 10, n = row & 1023;
            size_t off = ((size_t)(bb * 16 + h) * 1024 + n) * 32;
            float vv[8];
#pragma unroll
            for (int nt = 0; nt < 4; nt++) {
#pragma unroll
                for (int j = 0; j < 2; j++) {
                    int col = colbase + nt * 8 + 2 * tig + j;
                    vv[nt * 2 + j] = acc[mt][nt][rh * 2 + j] + bias[col];
                }
            }
            if (sec == 2) {
#pragma unroll
                for (int nt = 0; nt < 4; nt++) {
                    int d = nt * 8 + 2 * tig;
                    *(float2*)&dst[off + d] = make_float2(vv[nt * 2], vv[nt * 2 + 1]);
                }
            } else {
                float s = 0.f;
#pragma unroll
                for (int t = 0; t < 8; t++) s += vv[t];
                s += __shfl_xor_sync(0xffffffffu, s, 1);
                s += __shfl_xor_sync(0xffffffffu, s, 2);
                float mu = s * (1.f / 32.f);
                float sq = 0.f;
#pragma unroll
                for (int t = 0; t < 8; t++) { float d = vv[t] - mu; sq += d * d; }
                sq += __shfl_xor_sync(0xffffffffu, sq, 1);
                sq += __shfl_xor_sync(0xffffffffu, sq, 2);
                float rstd = rsqrtf(sq * (1.f / 32.f) + 1e-5f);
#pragma unroll
                for (int nt = 0; nt < 4; nt++) {
                    int d = nt * 8 + 2 * tig;
                    float y0 = (vv[nt * 2] - mu) * rstd * gam[d] + bet[d];
                    float y1 = (vv[nt * 2 + 1] - mu) * rstd * gam[d + 1] + bet[d + 1];
                    if (sec == 0) { y0 *= sc; y1 *= sc; }
                    *(float2*)&dst[off + d] = make_float2(y0, y1);
                }
            }
        }
    }
}

// ---------------- flash attention (fp16 MMA, reg-prefetched K/V) -----------
// grid (8 qblocks, 64 bh), 256 thr. Warp owns 16 q rows. 64-key tiles.
__global__ void flash_kernel(const float* __restrict__ q, const float* __restrict__ k,
                             const float* __restrict__ v, float* __restrict__ o) {
    __shared__ uint32_t Qs[128 * 20];
    __shared__ uint32_t Ks[64 * 20];
    __shared__ uint32_t Vs[32 * 36];
    __shared__ uint32_t Ps[8 * 16 * 36];

    int bh = blockIdx.y;
    int bm = blockIdx.x * 128;
    int b = bh >> 4, h = bh & 15;
    int tid = threadIdx.x;
    int w = tid >> 5, lane = tid & 31;
    int g = lane >> 2, tig = lane & 3;

    const float* qb = q + ((size_t)bh * 1024 + bm) * 32;
    const float* kb = k + (size_t)bh * 1024 * 32;
    const float* vb = v + (size_t)bh * 1024 * 32;

#pragma unroll
    for (int i = 0; i < 4; i++) {
        int idx = i * 256 + tid;
        int r = idx >> 3, dv = idx & 7;
        float4 t = *(const float4*)&qb[r * 32 + dv * 4];
        Qs[r * 20 + 2 * dv]     = h2u(__floats2half2_rn(t.x, t.y));
        Qs[r * 20 + 2 * dv + 1] = h2u(__floats2half2_rn(t.z, t.w));
    }

    // prefetch tile 0 into registers
    float4 k4[2];
    float va[4], vbx[4];
#pragma unroll
    for (int i = 0; i < 2; i++) {
        int idx = i * 256 + tid;
        int r = idx >> 3, dv = idx & 7;
        k4[i] = *(const float4*)&kb[(size_t)r * 32 + dv * 4];
    }
#pragma unroll
    for (int i = 0; i < 4; i++) {
        int idx = i * 256 + tid;
        int p = idx >> 5, d = idx & 31;
        va[i]  = vb[(size_t)(2 * p) * 32 + d];
        vbx[i] = vb[(size_t)(2 * p + 1) * 32 + d];
    }
    __syncthreads();

    uint32_t qa[2][4];
    int wr = w * 16;
#pragma unroll
    for (int ks = 0; ks < 2; ks++) {
        int kw = ks * 8;
        qa[ks][0] = Qs[(wr + g) * 20 + kw + tig];
        qa[ks][1] = Qs[(wr + 8 + g) * 20 + kw + tig];
        qa[ks][2] = Qs[(wr + g) * 20 + kw + 4 + tig];
        qa[ks][3] = Qs[(wr + 8 + g) * 20 + kw + 4 + tig];
    }

    float oacc[4][4] = {};
    float m0 = -1e30f, m1 = -1e30f, l0 = 0.f, l1 = 0.f;
    uint32_t* Pw = Ps + w * 16 * 36;

    for (int j = 0; j < 16; j++) {
        __syncthreads();   // prior reads of Ks/Vs complete
#pragma unroll
        for (int i = 0; i < 2; i++) {
            int idx = i * 256 + tid;
            int r = idx >> 3, dv = idx & 7;
            Ks[r * 20 + 2 * dv]     = h2u(__floats2half2_rn(k4[i].x, k4[i].y));
            Ks[r * 20 + 2 * dv + 1] = h2u(__floats2half2_rn(k4[i].z, k4[i].w));
        }
#pragma unroll
        for (int i = 0; i < 4; i++) {
            int idx = i * 256 + tid;
            int p = idx >> 5, d = idx & 31;
            Vs[d * 36 + p] = h2u(__floats2half2_rn(va[i], vbx[i]));
        }
        __syncthreads();
        if (j < 15) {      // prefetch next tile while computing this one
#pragma unroll
            for (int i = 0; i < 2; i++) {
                int idx = i * 256 + tid;
                int r = idx >> 3, dv = idx & 7;
                k4[i] = *(const float4*)&kb[(size_t)((j + 1) * 64 + r) * 32 + dv * 4];
            }
#pragma unroll
            for (int i = 0; i < 4; i++) {
                int idx = i * 256 + tid;
                int p = idx >> 5, d = idx & 31;
                va[i]  = vb[(size_t)((j + 1) * 64 + 2 * p) * 32 + d];
                vbx[i] = vb[(size_t)((j + 1) * 64 + 2 * p + 1) * 32 + d];
            }
        }

        // S = Q K^T : warp computes 16x64
        float s[8][4] = {};
#pragma unroll
        for (int ks = 0; ks < 2; ks++) {
            int kw = ks * 8;
            uint32_t bf[8][2];
#pragma unroll
            for (int nt = 0; nt < 8; nt++) {
                int nc = nt * 8;
                bf[nt][0] = Ks[(nc + g) * 20 + kw + tig];
                bf[nt][1] = Ks[(nc + g) * 20 + kw + 4 + tig];
            }
#pragma unroll
            for (int nt = 0; nt < 8; nt++)
                mma_f16(s[nt], qa[ks], bf[nt]);
        }

        // online softmax (rows g and g+8)
        float rm0 = -1e30f, rm1 = -1e30f;
#pragma unroll
        for (int nt = 0; nt < 8; nt++) {
            rm0 = fmaxf(rm0, fmaxf(s[nt][0], s[nt][1]));
            rm1 = fmaxf(rm1, fmaxf(s[nt][2], s[nt][3]));
        }
        rm0 = fmaxf(rm0, __shfl_xor_sync(0xffffffffu, rm0, 1));
        rm0 = fmaxf(rm0, __shfl_xor_sync(0xffffffffu, rm0, 2));
        rm1 = fmaxf(rm1, __shfl_xor_sync(0xffffffffu, rm1, 1));
        rm1 = fmaxf(rm1, __shfl_xor_sync(0xffffffffu, rm1, 2));
        float nm0 = fmaxf(m0, rm0), nm1 = fmaxf(m1, rm1);
        float al0 = __expf(m0 - nm0), al1 = __expf(m1 - nm1);
        float rs0 = 0.f, rs1 = 0.f;
#pragma unroll
        for (int nt = 0; nt < 8; nt++) {
            s[nt][0] = __expf(s[nt][0] - nm0);
            s[nt][1] = __expf(s[nt][1] - nm0);
            s[nt][2] = __expf(s[nt][2] - nm1);
            s[nt][3] = __expf(s[nt][3] - nm1);
            rs0 += s[nt][0] + s[nt][1];
            rs1 += s[nt][2] + s[nt][3];
        }
        rs0 += __shfl_xor_sync(0xffffffffu, rs0, 1);
        rs0 += __shfl_xor_sync(0xffffffffu, rs0, 2);
        rs1 += __shfl_xor_sync(0xffffffffu, rs1, 1);
        rs1 += __shfl_xor_sync(0xffffffffu, rs1, 2);
        l0 = l0 * al0 + rs0;
        l1 = l1 * al1 + rs1;
        m0 = nm0; m1 = nm1;
#pragma unroll
        for (int nt = 0; nt < 4; nt++) {
            oacc[nt][0] *= al0; oacc[nt][1] *= al0;
            oacc[nt][2] *= al1; oacc[nt][3] *= al1;
        }

#pragma unroll
        for (int nt = 0; nt < 8; nt++) {
            Pw[g * 36 + nt * 4 + tig]       = h2u(__floats2half2_rn(s[nt][0], s[nt][1]));
            Pw[(8 + g) * 36 + nt * 4 + tig] = h2u(__floats2half2_rn(s[nt][2], s[nt][3]));
        }
        __syncwarp();

#pragma unroll
        for (int ks2 = 0; ks2 < 4; ks2++) {
            int kw = ks2 * 8;
            uint32_t a[4];
            a[0] = Pw[g * 36 + kw + tig];
            a[1] = Pw[(8 + g) * 36 + kw + tig];
            a[2] = Pw[g * 36 + kw + 4 + tig];
            a[3] = Pw[(8 + g) * 36 + kw + 4 + tig];
            uint32_t bf[4][2];
#pragma unroll
            for (int nt = 0; nt < 4; nt++) {
                int nc = nt * 8;
                bf[nt][0] = Vs[(nc + g) * 36 + kw + tig];
                bf[nt][1] = Vs[(nc + g) * 36 + kw + 4 + tig];
            }
#pragma unroll
            for (int nt = 0; nt < 4; nt++)
                mma_f16(oacc[nt], a, bf[nt]);
        }
        __syncwarp();
    }

    float il0 = 1.f / l0, il1 = 1.f / l1;
    int n0 = bm + w * 16 + g;
#pragma unroll
    for (int nt = 0; nt < 4; nt++) {
        int col = h * 32 + nt * 8 + 2 * tig;
        o[((size_t)(b * 1024 + n0)) * 512 + col]     = oacc[nt][0] * il0;
        o[((size_t)(b * 1024 + n0)) * 512 + col + 1] = oacc[nt][1] * il0;
        o[((size_t)(b * 1024 + n0 + 8)) * 512 + col]     = oacc[nt][2] * il1;
        o[((size_t)(b * 1024 + n0 + 8)) * 512 + col + 1] = oacc[nt][3] * il1;
    }
}

// ---------------- unpatchify ----------------------------------------------
__global__ void unpatch_kernel(const float* __restrict__ fin, float* __restrict__ img) {
    int idx = blockIdx.x * blockDim.x + threadIdx.x;
    if (idx >= 4 * 64 * 128 * 128) return;
    int W = idx & 127;
    int H = (idx >> 7) & 127;
    int c = (idx >> 14) & 63;
    int b = idx >> 20;
    int hh = H >> 2, p = H & 3, ww = W >> 2, qq = W & 3;
    img[idx] = fin[((size_t)(b * 1024 + hh * 32 + ww)) * 1024 + c * 16 + p * 4 + qq];
}

// ---------------- conv1: smem-tiled 3x3, 64->16 ch, ReLU -------------------
__global__ void conv1_kernel(const float* __restrict__ img, const float* __restrict__ w,
                             const float* __restrict__ bias, float* __restrict__ out) {
    __shared__ float patch[18 * 18];
    __shared__ float wsm[16 * 9];
    int b = blockIdx.y;
    int tile = blockIdx.x;
    int Y0 = (tile >> 3) * 16, X0 = (tile & 7) * 16;
    int tid = threadIdx.x;
    int ty = tid >> 4, tx = tid & 15;
    float acc[16];
#pragma unroll
    for (int oc = 0; oc < 16; oc++) acc[oc] = bias[oc];

    for (int ic = 0; ic < 64; ic++) {
        __syncthreads();
        const float* ip = img + ((size_t)(b * 64 + ic)) * 16384;
        for (int idx = tid; idx < 324; idx += 256) {
            int py = idx / 18, px = idx % 18;
            int gy = Y0 + py - 1, gx = X0 + px - 1;
            patch[idx] = (gy >= 0 && gy < 128 && gx >= 0 && gx < 128) ? ip[gy * 128 + gx] : 0.f;
        }
        if (tid < 144) wsm[tid] = w[(size_t)((tid / 9) * 64 + ic) * 9 + (tid % 9)];
        __syncthreads();
        float p[9];
#pragma unroll
        for (int ky = 0; ky < 3; ky++)
#pragma unroll
            for (int kx = 0; kx < 3; kx++)
                p[ky * 3 + kx] = patch[(ty + ky) * 18 + tx + kx];
#pragma unroll
        for (int oc = 0; oc < 16; oc++) {
            float a = 0.f;
#pragma unroll
            for (int t = 0; t < 9; t++) a += p[t] * wsm[oc * 9 + t];
            acc[oc] += a;
        }
    }
#pragma unroll
    for (int oc = 0; oc < 16; oc++)
        out[((size_t)(b * 16 + oc)) * 16384 + (Y0 + ty) * 128 + X0 + tx] = fmaxf(acc[oc], 0.f);
}

// ---------------- conv2: 3x3, 16->3 ch -------------------------------------
__global__ void conv2_kernel(const float* __restrict__ img, const float* __restrict__ w,
                             const float* __restrict__ bias, float* __restrict__ out) {
    int idx = blockIdx.x * blockDim.x + threadIdx.x;
    if (idx >= 4 * 3 * 128 * 128) return;
    int x = idx & 127, y = (idx >> 7) & 127;
    int oc = (idx >> 14) % 3, b = idx / (3 * 16384);
    float acc = bias[oc];
    for (int ic = 0; ic < 16; ic++) {
        const float* ip = img + ((size_t)(b * 16 + ic)) * 16384;
        const float* wp = w + (size_t)(oc * 16 + ic) * 9;
#pragma unroll
        for (int ky = 0; ky < 3; ky++) {
            int yy = y + ky - 1;
            if (yy < 0 || yy > 127) continue;
#pragma unroll
            for (int kx = 0; kx < 3; kx++) {
                int xx = x + kx - 1;
                if (xx < 0 || xx > 127) continue;
                acc += ip[yy * 128 + xx] * wp[ky * 3 + kx];
            }
        }
    }
    out[idx] = acc;
}

// ---------------- driver ---------------------------------------------------
extern "C" void kernel_launch(void* const* d_in, const int* in_sizes, int n_in,
                              void* d_out, int out_size) {
    const float* x_in  = (const float*)d_in[0];
    const float* qkv_w = (const float*)d_in[1];
    const float* qkv_b = (const float*)d_in[2];
    const float* proj_w= (const float*)d_in[3];
    const float* proj_b= (const float*)d_in[4];
    const float* nq_g  = (const float*)d_in[5];
    const float* nq_b  = (const float*)d_in[6];
    const float* nk_g  = (const float*)d_in[7];
    const float* nk_b  = (const float*)d_in[8];
    const float* n1_g  = (const float*)d_in[9];
    const float* n1_b  = (const float*)d_in[10];
    const float* n2_g  = (const float*)d_in[11];
    const float* n2_b  = (const float*)d_in[12];
    const float* fc1_w = (const float*)d_in[13];
    const float* fc1_b = (const float*)d_in[14];
    const float* fc2_w = (const float*)d_in[15];
    const float* fc2_b = (const float*)d_in[16];
    const float* fin_w = (const float*)d_in[17];
    const float* fin_b = (const float*)d_in[18];
    const float* c1_w  = (const float*)d_in[19];
    const float* c1_b  = (const float*)d_in[20];
    const float* c2_w  = (const float*)d_in[21];
    const float* c2_b  = (const float*)d_in[22];
    float* out = (float*)d_out;

    float *px, *px2, *pln, *pmlp, *pq, *pk, *pv, *po, *pfin, *pimg, *pc1;
    cudaGetSymbolAddress((void**)&px,   g_x);
    cudaGetSymbolAddress((void**)&px2,  g_x2);
    cudaGetSymbolAddress((void**)&pln,  g_ln);
    cudaGetSymbolAddress((void**)&pmlp, g_mlp);
    cudaGetSymbolAddress((void**)&pq,   g_q);
    cudaGetSymbolAddress((void**)&pk,   g_k);
    cudaGetSymbolAddress((void**)&pv,   g_v);
    cudaGetSymbolAddress((void**)&po,   g_o);
    cudaGetSymbolAddress((void**)&pfin, g_fin);
    cudaGetSymbolAddress((void**)&pimg, g_img);
    cudaGetSymbolAddress((void**)&pc1,  g_c1);

    add_pe_kernel<<<(4 * 1024 * 512 + 255) / 256, 256>>>(x_in, px);

    for (int l = 0; l < 8; l++) {
        const float* qw = qkv_w + (size_t)l * 512 * 1536;
        const float* qb = qkv_b + (size_t)l * 1536;
        const float* pw = proj_w + (size_t)l * 512 * 512;
        const float* pb = proj_b + (size_t)l * 512;
        const float* f1w = fc1_w + (size_t)l * 512 * 2048;
        const float* f1b = fc1_b + (size_t)l * 2048;
        const float* f2w = fc2_w + (size_t)l * 2048 * 512;
        const float* f2b = fc2_b + (size_t)l * 512;

        ln_kernel<<<512, 256>>>(px, n1_g + l * 512, n1_b + l * 512, pln, 1e-5f);
        sgemm_qkv_kernel<<<dim3(12, 32), 256>>>(pln, qw, qb,
                                                nq_g + l * 32, nq_b + l * 32,
                                                nk_g + l * 32, nk_b + l * 32,
                                                pq, pk, pv);
        flash_kernel<<<dim3(8, 64), 256>>>(pq, pk, pv, po);
        sgemm_f16_kernel<<<dim3(4, 32), 256>>>(po, pw, pb, px, px2, 4096, 512, 512, 1);
        ln_kernel<<<512, 256>>>(px2, n2_g + l * 512, n2_b + l * 512, pln, 1e-5f);
        sgemm_f16_kernel<<<dim3(16, 32), 256>>>(pln, f1w, f1b, nullptr, pmlp, 4096, 2048, 512, 2);
        sgemm_f16_kernel<<<dim3(4, 32), 256>>>(pmlp, f2w, f2b, px2, px, 4096, 512, 2048, 1);
    }

    ln_kernel<<<512, 256>>>(px, nullptr, nullptr, pln, 1e-6f);
    sgemm_f16_kernel<<<dim3(8, 32), 256>>>(pln, fin_w, fin_b, nullptr, pfin, 4096, 1024, 512, 0);
    unpatch_kernel<<<(4 * 64 * 128 * 128 + 255) / 256, 256>>>(pfin, pimg);
    conv1_kernel<<<dim3(64, 4), 256>>>(pimg, c1_w, c1_b, pc1);
    conv2_kernel<<<(4 * 3 * 128 * 128 + 255) / 256, 256>>>(pc1, c2_w, c2_b, out);
}